// round 6
// baseline (speedup 1.0000x reference)
#include <cuda_runtime.h>
#include <cuda_bf16.h>
#include <cstdint>

// Problem constants (shapes fixed by the reference)
#define NMAX   50000
#define EMAX   800000
#define IND    128        // IN_DIM
#define HD     128        // HEADS * D
#define HEADS  8
#define DDIM   16

// Scratch for projected Q, K, V  ([N,128] each, fp32)
__device__ float g_Q[NMAX * HD];
__device__ float g_K[NMAX * HD];
__device__ float g_V[NMAX * HD];

// CSR-by-dst build scratch.
// INVARIANT: g_deg is all-zero at kernel_launch entry (BSS-zero initially;
// scan1 re-zeroes every element it reads, restoring the invariant each call).
__device__ int g_deg[NMAX];
__device__ int g_scantmp[NMAX];
__device__ int g_bsums[64];
__device__ int g_rowstart[NMAX + 1];
__device__ int g_cursor[NMAX];
__device__ int g_src_sorted[EMAX];

// ---------------------------------------------------------------------------
// QKV projection GEMM (tf32 tensor-core) + fused dst-degree histogram.
// The hist prologue is a grid-stride slice of the edge list per CTA; its
// loads/REDGs hide under the smem staging latency of the GEMM.
// ---------------------------------------------------------------------------
#define APAD 132
#define BPAD 136
#define GEMM_SMEM_BYTES ((128 * APAD + 128 * BPAD) * 4)

__device__ __forceinline__ uint32_t f32_to_tf32(float v) {
    uint32_t r;
    asm("cvt.rna.tf32.f32 %0, %1;" : "=r"(r) : "f"(v));
    return r;
}

__device__ __forceinline__ void mma_tf32(float c[4],
                                         uint32_t a0, uint32_t a1,
                                         uint32_t a2, uint32_t a3,
                                         uint32_t b0, uint32_t b1) {
    asm volatile(
        "mma.sync.aligned.m16n8k8.row.col.f32.tf32.tf32.f32 "
        "{%0,%1,%2,%3}, {%4,%5,%6,%7}, {%8,%9}, {%0,%1,%2,%3};"
        : "+f"(c[0]), "+f"(c[1]), "+f"(c[2]), "+f"(c[3])
        : "r"(a0), "r"(a1), "r"(a2), "r"(a3), "r"(b0), "r"(b1));
}

__global__ __launch_bounds__(256)
void qkv_gemm_hist(const float* __restrict__ h,
                   const float* __restrict__ Wq, const float* __restrict__ bq,
                   const float* __restrict__ Wk, const float* __restrict__ bk,
                   const float* __restrict__ Wv, const float* __restrict__ bv,
                   const int* __restrict__ dst,
                   int n_nodes, int n_edges)
{
    extern __shared__ uint32_t smem[];
    uint32_t* as = smem;                 // as[r*APAD + k]  (tf32 bits)
    uint32_t* ws = smem + 128 * APAD;    // ws[k*BPAD + n]  (tf32 bits)

    const float* W;
    const float* bias;
    float* out;
    if (blockIdx.y == 0)      { W = Wq; bias = bq; out = g_Q; }
    else if (blockIdx.y == 1) { W = Wk; bias = bk; out = g_K; }
    else                      { W = Wv; bias = bv; out = g_V; }

    const int row0 = blockIdx.x * 128;
    const int tid  = threadIdx.x;

    // Stage A (h tile) -> smem as tf32.
    #pragma unroll
    for (int i = 0; i < 64; i++) {
        int lin = tid + i * 256;
        int r = lin >> 7;
        int k = lin & 127;
        float v = 0.0f;
        int gr = row0 + r;
        if (gr < n_nodes) v = h[gr * IND + k];
        as[r * APAD + k] = f32_to_tf32(v);
    }
    // Stage W tile -> smem as tf32.
    #pragma unroll
    for (int i = 0; i < 64; i++) {
        int lin = tid + i * 256;
        int k = lin >> 7;
        int n = lin & 127;
        ws[k * BPAD + n] = f32_to_tf32(W[k * HD + n]);
    }

    // Fused histogram prologue: this CTA's slice of the edge list.
    // (independent of the staging above; overlaps with its latency)
    {
        int ncta  = gridDim.x * 3;
        int cta   = blockIdx.y * gridDim.x + blockIdx.x;
        int per   = (n_edges + ncta - 1) / ncta;
        int e0    = cta * per;
        int e1    = min(e0 + per, n_edges);
        for (int e = e0 + tid; e < e1; e += 256)
            atomicAdd(&g_deg[__ldg(dst + e)], 1);
    }
    __syncthreads();

    const int warp   = tid >> 5;
    const int lane   = tid & 31;
    const int g      = lane >> 2;       // 0..7
    const int t      = lane & 3;        // 0..3
    const int warp_m = warp & 3;        // 0..3
    const int warp_n = warp >> 2;       // 0..1

    float c[2][8][4];
    #pragma unroll
    for (int ni = 0; ni < 8; ni++) {
        int col = warp_n * 64 + ni * 8 + 2 * t;
        float b0 = bias[col];
        float b1 = bias[col + 1];
        #pragma unroll
        for (int mi = 0; mi < 2; mi++) {
            c[mi][ni][0] = b0; c[mi][ni][1] = b1;
            c[mi][ni][2] = b0; c[mi][ni][3] = b1;
        }
    }

    const uint32_t* a_base = as + (warp_m * 32 + g) * APAD;
    const uint32_t* b_base = ws + warp_n * 64 + g;

    #pragma unroll
    for (int kk = 0; kk < 16; kk++) {
        const int k0 = kk * 8;

        uint32_t a[2][4];
        #pragma unroll
        for (int mi = 0; mi < 2; mi++) {
            const uint32_t* ap = a_base + mi * 16 * APAD + k0 + t;
            a[mi][0] = ap[0];
            a[mi][1] = ap[8 * APAD];
            a[mi][2] = ap[4];
            a[mi][3] = ap[8 * APAD + 4];
        }

        uint32_t b[8][2];
        const uint32_t* bp = b_base + (k0 + t) * BPAD;
        #pragma unroll
        for (int ni = 0; ni < 8; ni++) {
            b[ni][0] = bp[ni * 8];
            b[ni][1] = bp[ni * 8 + 4 * BPAD];
        }

        #pragma unroll
        for (int mi = 0; mi < 2; mi++)
            #pragma unroll
            for (int ni = 0; ni < 8; ni++)
                mma_tf32(c[mi][ni], a[mi][0], a[mi][1], a[mi][2], a[mi][3],
                         b[ni][0], b[ni][1]);
    }

    #pragma unroll
    for (int mi = 0; mi < 2; mi++) {
        int r_lo = row0 + warp_m * 32 + mi * 16 + g;
        #pragma unroll
        for (int ni = 0; ni < 8; ni++) {
            int col = warp_n * 64 + ni * 8 + 2 * t;
            if (r_lo < n_nodes)
                *(float2*)&out[(size_t)r_lo * HD + col] =
                    make_float2(c[mi][ni][0], c[mi][ni][1]);
            if (r_lo + 8 < n_nodes)
                *(float2*)&out[(size_t)(r_lo + 8) * HD + col] =
                    make_float2(c[mi][ni][2], c[mi][ni][3]);
        }
    }
}

// ---------------------------------------------------------------------------
// scan1: per-block exclusive scan of g_deg (1024/block), emits block sums,
// and ZEROES g_deg behind itself (restores the all-zero invariant).
// ---------------------------------------------------------------------------
__global__ __launch_bounds__(1024)
void scan1_kernel(int n)
{
    __shared__ int wsum[32];
    int tid  = threadIdx.x;
    int lane = tid & 31, wid = tid >> 5;
    int i = blockIdx.x * 1024 + tid;
    int v = 0;
    if (i < n) {
        v = g_deg[i];
        g_deg[i] = 0;                 // self-restore for the next call
    }
    int x = v;
    #pragma unroll
    for (int o = 1; o < 32; o <<= 1) {
        int y = __shfl_up_sync(0xffffffffu, x, o);
        if (lane >= o) x += y;
    }
    if (lane == 31) wsum[wid] = x;
    __syncthreads();
    if (wid == 0) {
        int w = wsum[lane];
        #pragma unroll
        for (int o = 1; o < 32; o <<= 1) {
            int y = __shfl_up_sync(0xffffffffu, w, o);
            if (lane >= o) w += y;
        }
        wsum[lane] = w;  // inclusive warp totals
    }
    __syncthreads();
    int woff = (wid > 0) ? wsum[wid - 1] : 0;
    if (i < n) g_scantmp[i] = woff + x - v;          // exclusive within block
    if (tid == 1023) g_bsums[blockIdx.x] = woff + x; // block total
}

// ---------------------------------------------------------------------------
// scan23: every block redundantly exclusive-scans the (<=64) block sums
// in-register, then applies the offset to its 1024 elements and emits
// rowstart + cursor. rowstart[n] = n_edges.
// ---------------------------------------------------------------------------
__global__ __launch_bounds__(1024)
void scan23_kernel(int n, int nb, int n_edges)
{
    __shared__ int boffs_s[64];
    __shared__ int wtot;
    int tid = threadIdx.x;
    if (tid < 64) {
        int lane = tid & 31, wid2 = tid >> 5;
        int v = (tid < nb) ? g_bsums[tid] : 0;
        int x = v;
        #pragma unroll
        for (int o = 1; o < 32; o <<= 1) {
            int y = __shfl_up_sync(0xffffffffu, x, o);
            if (lane >= o) x += y;
        }
        if (tid == 31) wtot = x;      // total of first warp's 32 sums
        __syncwarp();
        boffs_s[tid] = x - v;         // exclusive within each 32-group
    }
    __syncthreads();
    int i = blockIdx.x * 1024 + tid;
    int blk = i >> 10;
    int boff = boffs_s[blk] + ((blk >= 32) ? wtot : 0);
    if (i < n) {
        int r = g_scantmp[i] + boff;
        g_rowstart[i] = r;
        g_cursor[i]   = r;
    }
    if (i == n) g_rowstart[n] = n_edges;
}

__global__ __launch_bounds__(256)
void scatter_kernel(const int* __restrict__ src, const int* __restrict__ dst,
                    int n_edges)
{
    int e = blockIdx.x * blockDim.x + threadIdx.x;
    if (e < n_edges) {
        int pos = atomicAdd(&g_cursor[dst[e]], 1);
        g_src_sorted[pos] = src[e];
    }
}

// ---------------------------------------------------------------------------
// Aggregation: one warp per destination node. No atomics.
// (unchanged from R5 passing version)
// ---------------------------------------------------------------------------
__global__ __launch_bounds__(256)
void aggregate_kernel(float* __restrict__ out, int n_nodes)
{
    int gtid = blockIdx.x * blockDim.x + threadIdx.x;
    int d    = gtid >> 5;
    int lane = gtid & 31;
    if (d >= n_nodes) return;

    const float4* K4 = (const float4*)g_K;
    const float4* Q4 = (const float4*)g_Q;
    const float4* V4 = (const float4*)g_V;

    float4 q = __ldg(&Q4[(size_t)d * 32 + lane]);
    int beg = g_rowstart[d];
    int end = g_rowstart[d + 1];

    float4 acc = make_float4(0.f, 0.f, 0.f, 0.f);

    int e = beg;
    for (; e + 4 <= end; e += 4) {
        int s0 = __ldg(g_src_sorted + e);
        int s1 = __ldg(g_src_sorted + e + 1);
        int s2 = __ldg(g_src_sorted + e + 2);
        int s3 = __ldg(g_src_sorted + e + 3);

        float4 k0 = __ldg(&K4[(size_t)s0 * 32 + lane]);
        float4 k1 = __ldg(&K4[(size_t)s1 * 32 + lane]);
        float4 k2 = __ldg(&K4[(size_t)s2 * 32 + lane]);
        float4 k3 = __ldg(&K4[(size_t)s3 * 32 + lane]);
        float4 v0 = __ldg(&V4[(size_t)s0 * 32 + lane]);
        float4 v1 = __ldg(&V4[(size_t)s1 * 32 + lane]);
        float4 v2 = __ldg(&V4[(size_t)s2 * 32 + lane]);
        float4 v3 = __ldg(&V4[(size_t)s3 * 32 + lane]);

        float p0 = k0.x*q.x + k0.y*q.y + k0.z*q.z + k0.w*q.w;
        float p1 = k1.x*q.x + k1.y*q.y + k1.z*q.z + k1.w*q.w;
        float p2 = k2.x*q.x + k2.y*q.y + k2.z*q.z + k2.w*q.w;
        float p3 = k3.x*q.x + k3.y*q.y + k3.z*q.z + k3.w*q.w;

        p0 += __shfl_xor_sync(0xffffffffu, p0, 1);
        p1 += __shfl_xor_sync(0xffffffffu, p1, 1);
        p2 += __shfl_xor_sync(0xffffffffu, p2, 1);
        p3 += __shfl_xor_sync(0xffffffffu, p3, 1);
        p0 += __shfl_xor_sync(0xffffffffu, p0, 2);
        p1 += __shfl_xor_sync(0xffffffffu, p1, 2);
        p2 += __shfl_xor_sync(0xffffffffu, p2, 2);
        p3 += __shfl_xor_sync(0xffffffffu, p3, 2);
        p0 *= 0.25f; p1 *= 0.25f; p2 *= 0.25f; p3 *= 0.25f;  // 1/sqrt(16)

        acc.x += p0*v0.x + p1*v1.x + p2*v2.x + p3*v3.x;
        acc.y += p0*v0.y + p1*v1.y + p2*v2.y + p3*v3.y;
        acc.z += p0*v0.z + p1*v1.z + p2*v2.z + p3*v3.z;
        acc.w += p0*v0.w + p1*v1.w + p2*v2.w + p3*v3.w;
    }
    for (; e < end; e++) {
        int s = __ldg(g_src_sorted + e);
        float4 kv = __ldg(&K4[(size_t)s * 32 + lane]);
        float p = kv.x*q.x + kv.y*q.y + kv.z*q.z + kv.w*q.w;
        p += __shfl_xor_sync(0xffffffffu, p, 1);
        p += __shfl_xor_sync(0xffffffffu, p, 2);
        p *= 0.25f;
        float4 v = __ldg(&V4[(size_t)s * 32 + lane]);
        acc.x += p*v.x; acc.y += p*v.y; acc.z += p*v.z; acc.w += p*v.w;
    }

    *(float4*)&out[(size_t)d * HD + lane * 4] = acc;
}

// ---------------------------------------------------------------------------
// Launch: 5 kernels (was 8).
//   [gemm+hist] -> scan1(+deg reset) -> scan23 -> scatter -> aggregate
// ---------------------------------------------------------------------------
extern "C" void kernel_launch(void* const* d_in, const int* in_sizes, int n_in,
                              void* d_out, int out_size)
{
    const float* h   = (const float*)d_in[0];
    const int*   src = (const int*)  d_in[1];
    const int*   dst = (const int*)  d_in[2];
    const float* Wq  = (const float*)d_in[3];
    const float* bq  = (const float*)d_in[4];
    const float* Wk  = (const float*)d_in[5];
    const float* bk  = (const float*)d_in[6];
    const float* Wv  = (const float*)d_in[7];
    const float* bv  = (const float*)d_in[8];
    float* out = (float*)d_out;

    int n_nodes = in_sizes[0] / IND;   // 50000
    int n_edges = in_sizes[1];         // 800000

    cudaFuncSetAttribute(qkv_gemm_hist,
                         cudaFuncAttributeMaxDynamicSharedMemorySize,
                         GEMM_SMEM_BYTES);

    // GEMM + fused histogram (g_deg is all-zero at entry by invariant).
    dim3 ggrid((n_nodes + 127) / 128, 3);
    qkv_gemm_hist<<<ggrid, 256, GEMM_SMEM_BYTES>>>(h, Wq, bq, Wk, bk, Wv, bv,
                                                   dst, n_nodes, n_edges);

    int nb = (n_nodes + 1023) / 1024;              // 49 for N=50000
    scan1_kernel<<<nb, 1024>>>(n_nodes);
    int nb1 = (n_nodes + 1 + 1023) / 1024;
    scan23_kernel<<<nb1, 1024>>>(n_nodes, nb, n_edges);

    int eb = (n_edges + 255) / 256;
    scatter_kernel<<<eb, 256>>>(src, dst, n_edges);

    int ablocks = (n_nodes * 32 + 255) / 256;
    aggregate_kernel<<<ablocks, 256>>>(out, n_nodes);
}

// round 7
// speedup vs baseline: 1.0536x; 1.0536x over previous
#include <cuda_runtime.h>
#include <cuda_bf16.h>
#include <cstdint>

// Problem constants (shapes fixed by the reference)
#define NMAX   50000
#define EMAX   800000
#define IND    128        // IN_DIM
#define HD     128        // HEADS * D
#define HEADS  8
#define DDIM   16

// Scratch for projected Q, K, V  ([N,128] each, fp32)
__device__ float g_Q[NMAX * HD];
__device__ float g_K[NMAX * HD];
__device__ float g_V[NMAX * HD];

// CSR-by-dst build scratch.
// INVARIANT: g_deg is all-zero at kernel_launch entry (BSS-zero initially;
// scan1 re-zeroes every element it reads, restoring the invariant each call).
__device__ int g_deg[NMAX];
__device__ int g_scantmp[NMAX];
__device__ int g_bsums[64];
__device__ int g_rowstart[NMAX + 1];
__device__ int g_cursor[NMAX];
__device__ int g_src_sorted[EMAX];

// ---------------------------------------------------------------------------
// QKV projection GEMM (tf32 tensor-core) — clean version, no fused hist.
// (R6 showed scattered-atomic work fused into this kernel costs ~15us.)
// ---------------------------------------------------------------------------
#define APAD 132
#define BPAD 136
#define GEMM_SMEM_BYTES ((128 * APAD + 128 * BPAD) * 4)

__device__ __forceinline__ uint32_t f32_to_tf32(float v) {
    uint32_t r;
    asm("cvt.rna.tf32.f32 %0, %1;" : "=r"(r) : "f"(v));
    return r;
}

__device__ __forceinline__ void mma_tf32(float c[4],
                                         uint32_t a0, uint32_t a1,
                                         uint32_t a2, uint32_t a3,
                                         uint32_t b0, uint32_t b1) {
    asm volatile(
        "mma.sync.aligned.m16n8k8.row.col.f32.tf32.tf32.f32 "
        "{%0,%1,%2,%3}, {%4,%5,%6,%7}, {%8,%9}, {%0,%1,%2,%3};"
        : "+f"(c[0]), "+f"(c[1]), "+f"(c[2]), "+f"(c[3])
        : "r"(a0), "r"(a1), "r"(a2), "r"(a3), "r"(b0), "r"(b1));
}

__global__ __launch_bounds__(256)
void qkv_gemm(const float* __restrict__ h,
              const float* __restrict__ Wq, const float* __restrict__ bq,
              const float* __restrict__ Wk, const float* __restrict__ bk,
              const float* __restrict__ Wv, const float* __restrict__ bv,
              int n_nodes)
{
    extern __shared__ uint32_t smem[];
    uint32_t* as = smem;                 // as[r*APAD + k]  (tf32 bits)
    uint32_t* ws = smem + 128 * APAD;    // ws[k*BPAD + n]  (tf32 bits)

    const float* W;
    const float* bias;
    float* out;
    if (blockIdx.y == 0)      { W = Wq; bias = bq; out = g_Q; }
    else if (blockIdx.y == 1) { W = Wk; bias = bk; out = g_K; }
    else                      { W = Wv; bias = bv; out = g_V; }

    const int row0 = blockIdx.x * 128;
    const int tid  = threadIdx.x;

    #pragma unroll
    for (int i = 0; i < 64; i++) {
        int lin = tid + i * 256;
        int r = lin >> 7;
        int k = lin & 127;
        float v = 0.0f;
        int gr = row0 + r;
        if (gr < n_nodes) v = h[gr * IND + k];
        as[r * APAD + k] = f32_to_tf32(v);
    }
    #pragma unroll
    for (int i = 0; i < 64; i++) {
        int lin = tid + i * 256;
        int k = lin >> 7;
        int n = lin & 127;
        ws[k * BPAD + n] = f32_to_tf32(W[k * HD + n]);
    }
    __syncthreads();

    const int warp   = tid >> 5;
    const int lane   = tid & 31;
    const int g      = lane >> 2;       // 0..7
    const int t      = lane & 3;        // 0..3
    const int warp_m = warp & 3;        // 0..3
    const int warp_n = warp >> 2;       // 0..1

    float c[2][8][4];
    #pragma unroll
    for (int ni = 0; ni < 8; ni++) {
        int col = warp_n * 64 + ni * 8 + 2 * t;
        float b0 = bias[col];
        float b1 = bias[col + 1];
        #pragma unroll
        for (int mi = 0; mi < 2; mi++) {
            c[mi][ni][0] = b0; c[mi][ni][1] = b1;
            c[mi][ni][2] = b0; c[mi][ni][3] = b1;
        }
    }

    const uint32_t* a_base = as + (warp_m * 32 + g) * APAD;
    const uint32_t* b_base = ws + warp_n * 64 + g;

    #pragma unroll
    for (int kk = 0; kk < 16; kk++) {
        const int k0 = kk * 8;

        uint32_t a[2][4];
        #pragma unroll
        for (int mi = 0; mi < 2; mi++) {
            const uint32_t* ap = a_base + mi * 16 * APAD + k0 + t;
            a[mi][0] = ap[0];
            a[mi][1] = ap[8 * APAD];
            a[mi][2] = ap[4];
            a[mi][3] = ap[8 * APAD + 4];
        }

        uint32_t b[8][2];
        const uint32_t* bp = b_base + (k0 + t) * BPAD;
        #pragma unroll
        for (int ni = 0; ni < 8; ni++) {
            b[ni][0] = bp[ni * 8];
            b[ni][1] = bp[ni * 8 + 4 * BPAD];
        }

        #pragma unroll
        for (int mi = 0; mi < 2; mi++)
            #pragma unroll
            for (int ni = 0; ni < 8; ni++)
                mma_tf32(c[mi][ni], a[mi][0], a[mi][1], a[mi][2], a[mi][3],
                         b[ni][0], b[ni][1]);
    }

    #pragma unroll
    for (int mi = 0; mi < 2; mi++) {
        int r_lo = row0 + warp_m * 32 + mi * 16 + g;
        #pragma unroll
        for (int ni = 0; ni < 8; ni++) {
            int col = warp_n * 64 + ni * 8 + 2 * t;
            if (r_lo < n_nodes)
                *(float2*)&out[(size_t)r_lo * HD + col] =
                    make_float2(c[mi][ni][0], c[mi][ni][1]);
            if (r_lo + 8 < n_nodes)
                *(float2*)&out[(size_t)(r_lo + 8) * HD + col] =
                    make_float2(c[mi][ni][2], c[mi][ni][3]);
        }
    }
}

// ---------------------------------------------------------------------------
// hist: dst-degree histogram, 4 edges/thread via int4 (MLP=4 on the REDGs).
// ---------------------------------------------------------------------------
__global__ __launch_bounds__(256)
void hist_kernel(const int* __restrict__ dst, int n_edges)
{
    int q = blockIdx.x * blockDim.x + threadIdx.x;   // quad index
    int e0 = q * 4;
    if (e0 + 4 <= n_edges) {
        int4 d4 = __ldg((const int4*)(dst + e0));
        atomicAdd(&g_deg[d4.x], 1);
        atomicAdd(&g_deg[d4.y], 1);
        atomicAdd(&g_deg[d4.z], 1);
        atomicAdd(&g_deg[d4.w], 1);
    } else {
        for (int e = e0; e < n_edges; e++)
            atomicAdd(&g_deg[__ldg(dst + e)], 1);
    }
}

// ---------------------------------------------------------------------------
// scan1: per-block exclusive scan of g_deg (1024/block), emits block sums,
// and ZEROES g_deg behind itself (restores the all-zero invariant).
// ---------------------------------------------------------------------------
__global__ __launch_bounds__(1024)
void scan1_kernel(int n)
{
    __shared__ int wsum[32];
    int tid  = threadIdx.x;
    int lane = tid & 31, wid = tid >> 5;
    int i = blockIdx.x * 1024 + tid;
    int v = 0;
    if (i < n) {
        v = g_deg[i];
        g_deg[i] = 0;                 // self-restore for the next call
    }
    int x = v;
    #pragma unroll
    for (int o = 1; o < 32; o <<= 1) {
        int y = __shfl_up_sync(0xffffffffu, x, o);
        if (lane >= o) x += y;
    }
    if (lane == 31) wsum[wid] = x;
    __syncthreads();
    if (wid == 0) {
        int w = wsum[lane];
        #pragma unroll
        for (int o = 1; o < 32; o <<= 1) {
            int y = __shfl_up_sync(0xffffffffu, w, o);
            if (lane >= o) w += y;
        }
        wsum[lane] = w;  // inclusive warp totals
    }
    __syncthreads();
    int woff = (wid > 0) ? wsum[wid - 1] : 0;
    if (i < n) g_scantmp[i] = woff + x - v;          // exclusive within block
    if (tid == 1023) g_bsums[blockIdx.x] = woff + x; // block total
}

// ---------------------------------------------------------------------------
// scan23: every block redundantly exclusive-scans the (<=64) block sums
// in-register, applies the offset, emits rowstart + cursor.
// ---------------------------------------------------------------------------
__global__ __launch_bounds__(1024)
void scan23_kernel(int n, int nb, int n_edges)
{
    __shared__ int boffs_s[64];
    __shared__ int wtot;
    int tid = threadIdx.x;
    if (tid < 64) {
        int lane = tid & 31;
        int v = (tid < nb) ? g_bsums[tid] : 0;
        int x = v;
        #pragma unroll
        for (int o = 1; o < 32; o <<= 1) {
            int y = __shfl_up_sync(0xffffffffu, x, o);
            if (lane >= o) x += y;
        }
        if (tid == 31) wtot = x;      // total of first warp's 32 sums
        __syncwarp();
        boffs_s[tid] = x - v;         // exclusive within each 32-group
    }
    __syncthreads();
    int i = blockIdx.x * 1024 + tid;
    int blk = i >> 10;
    int boff = boffs_s[blk] + ((blk >= 32) ? wtot : 0);
    if (i < n) {
        int r = g_scantmp[i] + boff;
        g_rowstart[i] = r;
        g_cursor[i]   = r;
    }
    if (i == n) g_rowstart[n] = n_edges;
}

// ---------------------------------------------------------------------------
// scatter: 4 edges/thread via int4 loads -> 4 independent ATOMGs in flight.
// ---------------------------------------------------------------------------
__global__ __launch_bounds__(256)
void scatter_kernel(const int* __restrict__ src, const int* __restrict__ dst,
                    int n_edges)
{
    int q = blockIdx.x * blockDim.x + threadIdx.x;
    int e0 = q * 4;
    if (e0 + 4 <= n_edges) {
        int4 s4 = __ldg((const int4*)(src + e0));
        int4 d4 = __ldg((const int4*)(dst + e0));
        int p0 = atomicAdd(&g_cursor[d4.x], 1);
        int p1 = atomicAdd(&g_cursor[d4.y], 1);
        int p2 = atomicAdd(&g_cursor[d4.z], 1);
        int p3 = atomicAdd(&g_cursor[d4.w], 1);
        g_src_sorted[p0] = s4.x;
        g_src_sorted[p1] = s4.y;
        g_src_sorted[p2] = s4.z;
        g_src_sorted[p3] = s4.w;
    } else {
        for (int e = e0; e < n_edges; e++) {
            int pos = atomicAdd(&g_cursor[__ldg(dst + e)], 1);
            g_src_sorted[pos] = __ldg(src + e);
        }
    }
}

// ---------------------------------------------------------------------------
// Aggregation: one warp per destination node. No atomics.
// (unchanged from R5 passing version)
// ---------------------------------------------------------------------------
__global__ __launch_bounds__(256)
void aggregate_kernel(float* __restrict__ out, int n_nodes)
{
    int gtid = blockIdx.x * blockDim.x + threadIdx.x;
    int d    = gtid >> 5;
    int lane = gtid & 31;
    if (d >= n_nodes) return;

    const float4* K4 = (const float4*)g_K;
    const float4* Q4 = (const float4*)g_Q;
    const float4* V4 = (const float4*)g_V;

    float4 q = __ldg(&Q4[(size_t)d * 32 + lane]);
    int beg = g_rowstart[d];
    int end = g_rowstart[d + 1];

    float4 acc = make_float4(0.f, 0.f, 0.f, 0.f);

    int e = beg;
    for (; e + 4 <= end; e += 4) {
        int s0 = __ldg(g_src_sorted + e);
        int s1 = __ldg(g_src_sorted + e + 1);
        int s2 = __ldg(g_src_sorted + e + 2);
        int s3 = __ldg(g_src_sorted + e + 3);

        float4 k0 = __ldg(&K4[(size_t)s0 * 32 + lane]);
        float4 k1 = __ldg(&K4[(size_t)s1 * 32 + lane]);
        float4 k2 = __ldg(&K4[(size_t)s2 * 32 + lane]);
        float4 k3 = __ldg(&K4[(size_t)s3 * 32 + lane]);
        float4 v0 = __ldg(&V4[(size_t)s0 * 32 + lane]);
        float4 v1 = __ldg(&V4[(size_t)s1 * 32 + lane]);
        float4 v2 = __ldg(&V4[(size_t)s2 * 32 + lane]);
        float4 v3 = __ldg(&V4[(size_t)s3 * 32 + lane]);

        float p0 = k0.x*q.x + k0.y*q.y + k0.z*q.z + k0.w*q.w;
        float p1 = k1.x*q.x + k1.y*q.y + k1.z*q.z + k1.w*q.w;
        float p2 = k2.x*q.x + k2.y*q.y + k2.z*q.z + k2.w*q.w;
        float p3 = k3.x*q.x + k3.y*q.y + k3.z*q.z + k3.w*q.w;

        p0 += __shfl_xor_sync(0xffffffffu, p0, 1);
        p1 += __shfl_xor_sync(0xffffffffu, p1, 1);
        p2 += __shfl_xor_sync(0xffffffffu, p2, 1);
        p3 += __shfl_xor_sync(0xffffffffu, p3, 1);
        p0 += __shfl_xor_sync(0xffffffffu, p0, 2);
        p1 += __shfl_xor_sync(0xffffffffu, p1, 2);
        p2 += __shfl_xor_sync(0xffffffffu, p2, 2);
        p3 += __shfl_xor_sync(0xffffffffu, p3, 2);
        p0 *= 0.25f; p1 *= 0.25f; p2 *= 0.25f; p3 *= 0.25f;  // 1/sqrt(16)

        acc.x += p0*v0.x + p1*v1.x + p2*v2.x + p3*v3.x;
        acc.y += p0*v0.y + p1*v1.y + p2*v2.y + p3*v3.y;
        acc.z += p0*v0.z + p1*v1.z + p2*v2.z + p3*v3.z;
        acc.w += p0*v0.w + p1*v1.w + p2*v2.w + p3*v3.w;
    }
    for (; e < end; e++) {
        int s = __ldg(g_src_sorted + e);
        float4 kv = __ldg(&K4[(size_t)s * 32 + lane]);
        float p = kv.x*q.x + kv.y*q.y + kv.z*q.z + kv.w*q.w;
        p += __shfl_xor_sync(0xffffffffu, p, 1);
        p += __shfl_xor_sync(0xffffffffu, p, 2);
        p *= 0.25f;
        float4 v = __ldg(&V4[(size_t)s * 32 + lane]);
        acc.x += p*v.x; acc.y += p*v.y; acc.z += p*v.z; acc.w += p*v.w;
    }

    *(float4*)&out[(size_t)d * HD + lane * 4] = acc;
}

// ---------------------------------------------------------------------------
// Launch: gemm -> hist -> scan1 -> scan23 -> scatter -> aggregate
// ---------------------------------------------------------------------------
extern "C" void kernel_launch(void* const* d_in, const int* in_sizes, int n_in,
                              void* d_out, int out_size)
{
    const float* h   = (const float*)d_in[0];
    const int*   src = (const int*)  d_in[1];
    const int*   dst = (const int*)  d_in[2];
    const float* Wq  = (const float*)d_in[3];
    const float* bq  = (const float*)d_in[4];
    const float* Wk  = (const float*)d_in[5];
    const float* bk  = (const float*)d_in[6];
    const float* Wv  = (const float*)d_in[7];
    const float* bv  = (const float*)d_in[8];
    float* out = (float*)d_out;

    int n_nodes = in_sizes[0] / IND;   // 50000
    int n_edges = in_sizes[1];         // 800000

    cudaFuncSetAttribute(qkv_gemm,
                         cudaFuncAttributeMaxDynamicSharedMemorySize,
                         GEMM_SMEM_BYTES);

    dim3 ggrid((n_nodes + 127) / 128, 3);
    qkv_gemm<<<ggrid, 256, GEMM_SMEM_BYTES>>>(h, Wq, bq, Wk, bk, Wv, bv, n_nodes);

    int nquad = (n_edges + 3) / 4;
    int qb = (nquad + 255) / 256;
    hist_kernel<<<qb, 256>>>(dst, n_edges);

    int nb = (n_nodes + 1023) / 1024;              // 49 for N=50000
    scan1_kernel<<<nb, 1024>>>(n_nodes);
    int nb1 = (n_nodes + 1 + 1023) / 1024;
    scan23_kernel<<<nb1, 1024>>>(n_nodes, nb, n_edges);

    scatter_kernel<<<qb, 256>>>(src, dst, n_edges);

    int ablocks = (n_nodes * 32 + 255) / 256;
    aggregate_kernel<<<ablocks, 256>>>(out, n_nodes);
}

// round 8
// speedup vs baseline: 1.1057x; 1.0494x over previous
#include <cuda_runtime.h>
#include <cuda_bf16.h>
#include <cuda_fp16.h>
#include <cstdint>

// Problem constants (shapes fixed by the reference)
#define NMAX   50000
#define EMAX   800000
#define IND    128        // IN_DIM
#define HD     128        // HEADS * D
#define HEADS  8
#define DDIM   16

// Scratch: Q fp32 (streamed once), K/V fp16 (gathered 16x each -> bytes matter)
__device__ float  g_Q[NMAX * HD];
__device__ __align__(16) __half g_Kh[NMAX * HD];
__device__ __align__(16) __half g_Vh[NMAX * HD];

// CSR-by-dst build scratch.
// INVARIANT: g_deg is all-zero at kernel_launch entry (BSS-zero initially;
// scan1 re-zeroes every element it reads, restoring the invariant each call).
__device__ int g_deg[NMAX];
__device__ int g_scantmp[NMAX];
__device__ int g_bsums[64];
__device__ int g_rowstart[NMAX + 1];
__device__ int g_cursor[NMAX];
__device__ int g_src_sorted[EMAX];

// ---------------------------------------------------------------------------
// QKV projection GEMM (tf32 tensor-core). Q written fp32; K/V written fp16.
// ---------------------------------------------------------------------------
#define APAD 132
#define BPAD 136
#define GEMM_SMEM_BYTES ((128 * APAD + 128 * BPAD) * 4)

__device__ __forceinline__ uint32_t f32_to_tf32(float v) {
    uint32_t r;
    asm("cvt.rna.tf32.f32 %0, %1;" : "=r"(r) : "f"(v));
    return r;
}

__device__ __forceinline__ void mma_tf32(float c[4],
                                         uint32_t a0, uint32_t a1,
                                         uint32_t a2, uint32_t a3,
                                         uint32_t b0, uint32_t b1) {
    asm volatile(
        "mma.sync.aligned.m16n8k8.row.col.f32.tf32.tf32.f32 "
        "{%0,%1,%2,%3}, {%4,%5,%6,%7}, {%8,%9}, {%0,%1,%2,%3};"
        : "+f"(c[0]), "+f"(c[1]), "+f"(c[2]), "+f"(c[3])
        : "r"(a0), "r"(a1), "r"(a2), "r"(a3), "r"(b0), "r"(b1));
}

__global__ __launch_bounds__(256)
void qkv_gemm(const float* __restrict__ h,
              const float* __restrict__ Wq, const float* __restrict__ bq,
              const float* __restrict__ Wk, const float* __restrict__ bk,
              const float* __restrict__ Wv, const float* __restrict__ bv,
              int n_nodes)
{
    extern __shared__ uint32_t smem[];
    uint32_t* as = smem;                 // as[r*APAD + k]  (tf32 bits)
    uint32_t* ws = smem + 128 * APAD;    // ws[k*BPAD + n]  (tf32 bits)

    const float* W;
    const float* bias;
    if (blockIdx.y == 0)      { W = Wq; bias = bq; }
    else if (blockIdx.y == 1) { W = Wk; bias = bk; }
    else                      { W = Wv; bias = bv; }

    const int row0 = blockIdx.x * 128;
    const int tid  = threadIdx.x;

    #pragma unroll
    for (int i = 0; i < 64; i++) {
        int lin = tid + i * 256;
        int r = lin >> 7;
        int k = lin & 127;
        float v = 0.0f;
        int gr = row0 + r;
        if (gr < n_nodes) v = h[gr * IND + k];
        as[r * APAD + k] = f32_to_tf32(v);
    }
    #pragma unroll
    for (int i = 0; i < 64; i++) {
        int lin = tid + i * 256;
        int k = lin >> 7;
        int n = lin & 127;
        ws[k * BPAD + n] = f32_to_tf32(W[k * HD + n]);
    }
    __syncthreads();

    const int warp   = tid >> 5;
    const int lane   = tid & 31;
    const int g      = lane >> 2;       // 0..7
    const int t      = lane & 3;        // 0..3
    const int warp_m = warp & 3;        // 0..3
    const int warp_n = warp >> 2;       // 0..1

    float c[2][8][4];
    #pragma unroll
    for (int ni = 0; ni < 8; ni++) {
        int col = warp_n * 64 + ni * 8 + 2 * t;
        float b0 = bias[col];
        float b1 = bias[col + 1];
        #pragma unroll
        for (int mi = 0; mi < 2; mi++) {
            c[mi][ni][0] = b0; c[mi][ni][1] = b1;
            c[mi][ni][2] = b0; c[mi][ni][3] = b1;
        }
    }

    const uint32_t* a_base = as + (warp_m * 32 + g) * APAD;
    const uint32_t* b_base = ws + warp_n * 64 + g;

    #pragma unroll
    for (int kk = 0; kk < 16; kk++) {
        const int k0 = kk * 8;

        uint32_t a[2][4];
        #pragma unroll
        for (int mi = 0; mi < 2; mi++) {
            const uint32_t* ap = a_base + mi * 16 * APAD + k0 + t;
            a[mi][0] = ap[0];
            a[mi][1] = ap[8 * APAD];
            a[mi][2] = ap[4];
            a[mi][3] = ap[8 * APAD + 4];
        }

        uint32_t b[8][2];
        const uint32_t* bp = b_base + (k0 + t) * BPAD;
        #pragma unroll
        for (int ni = 0; ni < 8; ni++) {
            b[ni][0] = bp[ni * 8];
            b[ni][1] = bp[ni * 8 + 4 * BPAD];
        }

        #pragma unroll
        for (int mi = 0; mi < 2; mi++)
            #pragma unroll
            for (int ni = 0; ni < 8; ni++)
                mma_tf32(c[mi][ni], a[mi][0], a[mi][1], a[mi][2], a[mi][3],
                         b[ni][0], b[ni][1]);
    }

    if (blockIdx.y == 0) {
        // Q: fp32 stores.
        #pragma unroll
        for (int mi = 0; mi < 2; mi++) {
            int r_lo = row0 + warp_m * 32 + mi * 16 + g;
            #pragma unroll
            for (int ni = 0; ni < 8; ni++) {
                int col = warp_n * 64 + ni * 8 + 2 * t;
                if (r_lo < n_nodes)
                    *(float2*)&g_Q[(size_t)r_lo * HD + col] =
                        make_float2(c[mi][ni][0], c[mi][ni][1]);
                if (r_lo + 8 < n_nodes)
                    *(float2*)&g_Q[(size_t)(r_lo + 8) * HD + col] =
                        make_float2(c[mi][ni][2], c[mi][ni][3]);
            }
        }
    } else {
        // K/V: fp16 stores (half2 = 4B per pair, col is even).
        __half* outh = (blockIdx.y == 1) ? g_Kh : g_Vh;
        #pragma unroll
        for (int mi = 0; mi < 2; mi++) {
            int r_lo = row0 + warp_m * 32 + mi * 16 + g;
            #pragma unroll
            for (int ni = 0; ni < 8; ni++) {
                int col = warp_n * 64 + ni * 8 + 2 * t;
                if (r_lo < n_nodes)
                    *(__half2*)&outh[(size_t)r_lo * HD + col] =
                        __floats2half2_rn(c[mi][ni][0], c[mi][ni][1]);
                if (r_lo + 8 < n_nodes)
                    *(__half2*)&outh[(size_t)(r_lo + 8) * HD + col] =
                        __floats2half2_rn(c[mi][ni][2], c[mi][ni][3]);
            }
        }
    }
}

// ---------------------------------------------------------------------------
// hist: dst-degree histogram, 4 edges/thread via int4 (MLP=4 on the REDGs).
// ---------------------------------------------------------------------------
__global__ __launch_bounds__(256)
void hist_kernel(const int* __restrict__ dst, int n_edges)
{
    int q = blockIdx.x * blockDim.x + threadIdx.x;   // quad index
    int e0 = q * 4;
    if (e0 + 4 <= n_edges) {
        int4 d4 = __ldg((const int4*)(dst + e0));
        atomicAdd(&g_deg[d4.x], 1);
        atomicAdd(&g_deg[d4.y], 1);
        atomicAdd(&g_deg[d4.z], 1);
        atomicAdd(&g_deg[d4.w], 1);
    } else {
        for (int e = e0; e < n_edges; e++)
            atomicAdd(&g_deg[__ldg(dst + e)], 1);
    }
}

// ---------------------------------------------------------------------------
// scan1: per-block exclusive scan of g_deg (1024/block), emits block sums,
// and ZEROES g_deg behind itself (restores the all-zero invariant).
// ---------------------------------------------------------------------------
__global__ __launch_bounds__(1024)
void scan1_kernel(int n)
{
    __shared__ int wsum[32];
    int tid  = threadIdx.x;
    int lane = tid & 31, wid = tid >> 5;
    int i = blockIdx.x * 1024 + tid;
    int v = 0;
    if (i < n) {
        v = g_deg[i];
        g_deg[i] = 0;                 // self-restore for the next call
    }
    int x = v;
    #pragma unroll
    for (int o = 1; o < 32; o <<= 1) {
        int y = __shfl_up_sync(0xffffffffu, x, o);
        if (lane >= o) x += y;
    }
    if (lane == 31) wsum[wid] = x;
    __syncthreads();
    if (wid == 0) {
        int w = wsum[lane];
        #pragma unroll
        for (int o = 1; o < 32; o <<= 1) {
            int y = __shfl_up_sync(0xffffffffu, w, o);
            if (lane >= o) w += y;
        }
        wsum[lane] = w;  // inclusive warp totals
    }
    __syncthreads();
    int woff = (wid > 0) ? wsum[wid - 1] : 0;
    if (i < n) g_scantmp[i] = woff + x - v;          // exclusive within block
    if (tid == 1023) g_bsums[blockIdx.x] = woff + x; // block total
}

// ---------------------------------------------------------------------------
// scan23: every block redundantly exclusive-scans the (<=64) block sums
// in-register, applies the offset, emits rowstart + cursor.
// ---------------------------------------------------------------------------
__global__ __launch_bounds__(1024)
void scan23_kernel(int n, int nb, int n_edges)
{
    __shared__ int boffs_s[64];
    __shared__ int wtot;
    int tid = threadIdx.x;
    if (tid < 64) {
        int lane = tid & 31;
        int v = (tid < nb) ? g_bsums[tid] : 0;
        int x = v;
        #pragma unroll
        for (int o = 1; o < 32; o <<= 1) {
            int y = __shfl_up_sync(0xffffffffu, x, o);
            if (lane >= o) x += y;
        }
        if (tid == 31) wtot = x;      // total of first warp's 32 sums
        __syncwarp();
        boffs_s[tid] = x - v;         // exclusive within each 32-group
    }
    __syncthreads();
    int i = blockIdx.x * 1024 + tid;
    int blk = i >> 10;
    int boff = boffs_s[blk] + ((blk >= 32) ? wtot : 0);
    if (i < n) {
        int r = g_scantmp[i] + boff;
        g_rowstart[i] = r;
        g_cursor[i]   = r;
    }
    if (i == n) g_rowstart[n] = n_edges;
}

// ---------------------------------------------------------------------------
// scatter: 4 edges/thread via int4 loads -> 4 independent ATOMGs in flight.
// ---------------------------------------------------------------------------
__global__ __launch_bounds__(256)
void scatter_kernel(const int* __restrict__ src, const int* __restrict__ dst,
                    int n_edges)
{
    int q = blockIdx.x * blockDim.x + threadIdx.x;
    int e0 = q * 4;
    if (e0 + 4 <= n_edges) {
        int4 s4 = __ldg((const int4*)(src + e0));
        int4 d4 = __ldg((const int4*)(dst + e0));
        int p0 = atomicAdd(&g_cursor[d4.x], 1);
        int p1 = atomicAdd(&g_cursor[d4.y], 1);
        int p2 = atomicAdd(&g_cursor[d4.z], 1);
        int p3 = atomicAdd(&g_cursor[d4.w], 1);
        g_src_sorted[p0] = s4.x;
        g_src_sorted[p1] = s4.y;
        g_src_sorted[p2] = s4.z;
        g_src_sorted[p3] = s4.w;
    } else {
        for (int e = e0; e < n_edges; e++) {
            int pos = atomicAdd(&g_cursor[__ldg(dst + e)], 1);
            g_src_sorted[pos] = __ldg(src + e);
        }
    }
}

// ---------------------------------------------------------------------------
// Aggregation: one warp per destination node, no atomics.
// K/V gathered as fp16 (8B uint2 per lane per node), converted to fp32 in
// registers; all arithmetic stays fp32.
// ---------------------------------------------------------------------------
__device__ __forceinline__ float4 h4_to_f4(uint2 u) {
    float2 a = __half22float2(*(__half2*)&u.x);
    float2 b = __half22float2(*(__half2*)&u.y);
    return make_float4(a.x, a.y, b.x, b.y);
}

__global__ __launch_bounds__(256)
void aggregate_kernel(float* __restrict__ out, int n_nodes)
{
    int gtid = blockIdx.x * blockDim.x + threadIdx.x;
    int d    = gtid >> 5;
    int lane = gtid & 31;
    if (d >= n_nodes) return;

    const float4* Q4 = (const float4*)g_Q;
    const uint2*  K2 = (const uint2*)g_Kh;   // node stride: 32 uint2 (128 half)
    const uint2*  V2 = (const uint2*)g_Vh;

    float4 q = __ldg(&Q4[(size_t)d * 32 + lane]);
    int beg = g_rowstart[d];
    int end = g_rowstart[d + 1];

    float4 acc = make_float4(0.f, 0.f, 0.f, 0.f);

    int e = beg;
    for (; e + 4 <= end; e += 4) {
        int s0 = __ldg(g_src_sorted + e);
        int s1 = __ldg(g_src_sorted + e + 1);
        int s2 = __ldg(g_src_sorted + e + 2);
        int s3 = __ldg(g_src_sorted + e + 3);

        uint2 ku0 = __ldg(&K2[(size_t)s0 * 32 + lane]);
        uint2 ku1 = __ldg(&K2[(size_t)s1 * 32 + lane]);
        uint2 ku2 = __ldg(&K2[(size_t)s2 * 32 + lane]);
        uint2 ku3 = __ldg(&K2[(size_t)s3 * 32 + lane]);
        uint2 vu0 = __ldg(&V2[(size_t)s0 * 32 + lane]);
        uint2 vu1 = __ldg(&V2[(size_t)s1 * 32 + lane]);
        uint2 vu2 = __ldg(&V2[(size_t)s2 * 32 + lane]);
        uint2 vu3 = __ldg(&V2[(size_t)s3 * 32 + lane]);

        float4 k0 = h4_to_f4(ku0), k1 = h4_to_f4(ku1);
        float4 k2 = h4_to_f4(ku2), k3 = h4_to_f4(ku3);

        float p0 = k0.x*q.x + k0.y*q.y + k0.z*q.z + k0.w*q.w;
        float p1 = k1.x*q.x + k1.y*q.y + k1.z*q.z + k1.w*q.w;
        float p2 = k2.x*q.x + k2.y*q.y + k2.z*q.z + k2.w*q.w;
        float p3 = k3.x*q.x + k3.y*q.y + k3.z*q.z + k3.w*q.w;

        p0 += __shfl_xor_sync(0xffffffffu, p0, 1);
        p1 += __shfl_xor_sync(0xffffffffu, p1, 1);
        p2 += __shfl_xor_sync(0xffffffffu, p2, 1);
        p3 += __shfl_xor_sync(0xffffffffu, p3, 1);
        p0 += __shfl_xor_sync(0xffffffffu, p0, 2);
        p1 += __shfl_xor_sync(0xffffffffu, p1, 2);
        p2 += __shfl_xor_sync(0xffffffffu, p2, 2);
        p3 += __shfl_xor_sync(0xffffffffu, p3, 2);
        p0 *= 0.25f; p1 *= 0.25f; p2 *= 0.25f; p3 *= 0.25f;  // 1/sqrt(16)

        float4 v0 = h4_to_f4(vu0), v1 = h4_to_f4(vu1);
        float4 v2 = h4_to_f4(vu2), v3 = h4_to_f4(vu3);

        acc.x += p0*v0.x + p1*v1.x + p2*v2.x + p3*v3.x;
        acc.y += p0*v0.y + p1*v1.y + p2*v2.y + p3*v3.y;
        acc.z += p0*v0.z + p1*v1.z + p2*v2.z + p3*v3.z;
        acc.w += p0*v0.w + p1*v1.w + p2*v2.w + p3*v3.w;
    }
    for (; e < end; e++) {
        int s = __ldg(g_src_sorted + e);
        float4 kv = h4_to_f4(__ldg(&K2[(size_t)s * 32 + lane]));
        float p = kv.x*q.x + kv.y*q.y + kv.z*q.z + kv.w*q.w;
        p += __shfl_xor_sync(0xffffffffu, p, 1);
        p += __shfl_xor_sync(0xffffffffu, p, 2);
        p *= 0.25f;
        float4 v = h4_to_f4(__ldg(&V2[(size_t)s * 32 + lane]));
        acc.x += p*v.x; acc.y += p*v.y; acc.z += p*v.z; acc.w += p*v.w;
    }

    *(float4*)&out[(size_t)d * HD + lane * 4] = acc;
}

// ---------------------------------------------------------------------------
// Launch: gemm -> hist -> scan1 -> scan23 -> scatter -> aggregate
// ---------------------------------------------------------------------------
extern "C" void kernel_launch(void* const* d_in, const int* in_sizes, int n_in,
                              void* d_out, int out_size)
{
    const float* h   = (const float*)d_in[0];
    const int*   src = (const int*)  d_in[1];
    const int*   dst = (const int*)  d_in[2];
    const float* Wq  = (const float*)d_in[3];
    const float* bq  = (const float*)d_in[4];
    const float* Wk  = (const float*)d_in[5];
    const float* bk  = (const float*)d_in[6];
    const float* Wv  = (const float*)d_in[7];
    const float* bv  = (const float*)d_in[8];
    float* out = (float*)d_out;

    int n_nodes = in_sizes[0] / IND;   // 50000
    int n_edges = in_sizes[1];         // 800000

    cudaFuncSetAttribute(qkv_gemm,
                         cudaFuncAttributeMaxDynamicSharedMemorySize,
                         GEMM_SMEM_BYTES);

    dim3 ggrid((n_nodes + 127) / 128, 3);
    qkv_gemm<<<ggrid, 256, GEMM_SMEM_BYTES>>>(h, Wq, bq, Wk, bk, Wv, bv, n_nodes);

    int nquad = (n_edges + 3) / 4;
    int qb = (nquad + 255) / 256;
    hist_kernel<<<qb, 256>>>(dst, n_edges);

    int nb = (n_nodes + 1023) / 1024;              // 49 for N=50000
    scan1_kernel<<<nb, 1024>>>(n_nodes);
    int nb1 = (n_nodes + 1 + 1023) / 1024;
    scan23_kernel<<<nb1, 1024>>>(n_nodes, nb, n_edges);

    scatter_kernel<<<qb, 256>>>(src, dst, n_edges);

    int ablocks = (n_nodes * 32 + 255) / 256;
    aggregate_kernel<<<ablocks, 256>>>(out, n_nodes);
}

// round 9
// speedup vs baseline: 1.1437x; 1.0344x over previous
#include <cuda_runtime.h>
#include <cuda_bf16.h>
#include <cuda_fp16.h>
#include <cstdint>

// Problem constants (shapes fixed by the reference)
#define NMAX   50000
#define EMAX   800000
#define IND    128        // IN_DIM
#define HD     128        // HEADS * D
#define HEADS  8
#define DDIM   16

// Scratch: Q fp32 (streamed once), K/V fp16 (gathered 16x each -> bytes matter)
__device__ float  g_Q[NMAX * HD];
__device__ __align__(16) __half g_Kh[NMAX * HD];
__device__ __align__(16) __half g_Vh[NMAX * HD];

// CSR-by-dst build scratch.
// INVARIANT: g_deg is all-zero at kernel_launch entry (BSS-zero initially;
// scan1 re-zeroes every element it reads, restoring the invariant each call).
__device__ int g_deg[NMAX];
__device__ int g_scantmp[NMAX];
__device__ int g_bsums[64];
__device__ int g_rowstart[NMAX + 1];
__device__ int g_cursor[NMAX];
__device__ int g_src_sorted[EMAX];

// ---------------------------------------------------------------------------
// QKV projection GEMM (tf32 tensor-core). Q written fp32; K/V written fp16.
// ---------------------------------------------------------------------------
#define APAD 132
#define BPAD 136
#define GEMM_SMEM_BYTES ((128 * APAD + 128 * BPAD) * 4)

__device__ __forceinline__ uint32_t f32_to_tf32(float v) {
    uint32_t r;
    asm("cvt.rna.tf32.f32 %0, %1;" : "=r"(r) : "f"(v));
    return r;
}

__device__ __forceinline__ void mma_tf32(float c[4],
                                         uint32_t a0, uint32_t a1,
                                         uint32_t a2, uint32_t a3,
                                         uint32_t b0, uint32_t b1) {
    asm volatile(
        "mma.sync.aligned.m16n8k8.row.col.f32.tf32.tf32.f32 "
        "{%0,%1,%2,%3}, {%4,%5,%6,%7}, {%8,%9}, {%0,%1,%2,%3};"
        : "+f"(c[0]), "+f"(c[1]), "+f"(c[2]), "+f"(c[3])
        : "r"(a0), "r"(a1), "r"(a2), "r"(a3), "r"(b0), "r"(b1));
}

__global__ __launch_bounds__(256)
void qkv_gemm(const float* __restrict__ h,
              const float* __restrict__ Wq, const float* __restrict__ bq,
              const float* __restrict__ Wk, const float* __restrict__ bk,
              const float* __restrict__ Wv, const float* __restrict__ bv,
              int n_nodes)
{
    extern __shared__ uint32_t smem[];
    uint32_t* as = smem;                 // as[r*APAD + k]  (tf32 bits)
    uint32_t* ws = smem + 128 * APAD;    // ws[k*BPAD + n]  (tf32 bits)

    const float* W;
    const float* bias;
    if (blockIdx.y == 0)      { W = Wq; bias = bq; }
    else if (blockIdx.y == 1) { W = Wk; bias = bk; }
    else                      { W = Wv; bias = bv; }

    const int row0 = blockIdx.x * 128;
    const int tid  = threadIdx.x;

    #pragma unroll
    for (int i = 0; i < 64; i++) {
        int lin = tid + i * 256;
        int r = lin >> 7;
        int k = lin & 127;
        float v = 0.0f;
        int gr = row0 + r;
        if (gr < n_nodes) v = h[gr * IND + k];
        as[r * APAD + k] = f32_to_tf32(v);
    }
    #pragma unroll
    for (int i = 0; i < 64; i++) {
        int lin = tid + i * 256;
        int k = lin >> 7;
        int n = lin & 127;
        ws[k * BPAD + n] = f32_to_tf32(W[k * HD + n]);
    }
    __syncthreads();

    const int warp   = tid >> 5;
    const int lane   = tid & 31;
    const int g      = lane >> 2;       // 0..7
    const int t      = lane & 3;        // 0..3
    const int warp_m = warp & 3;        // 0..3
    const int warp_n = warp >> 2;       // 0..1

    float c[2][8][4];
    #pragma unroll
    for (int ni = 0; ni < 8; ni++) {
        int col = warp_n * 64 + ni * 8 + 2 * t;
        float b0 = bias[col];
        float b1 = bias[col + 1];
        #pragma unroll
        for (int mi = 0; mi < 2; mi++) {
            c[mi][ni][0] = b0; c[mi][ni][1] = b1;
            c[mi][ni][2] = b0; c[mi][ni][3] = b1;
        }
    }

    const uint32_t* a_base = as + (warp_m * 32 + g) * APAD;
    const uint32_t* b_base = ws + warp_n * 64 + g;

    #pragma unroll
    for (int kk = 0; kk < 16; kk++) {
        const int k0 = kk * 8;

        uint32_t a[2][4];
        #pragma unroll
        for (int mi = 0; mi < 2; mi++) {
            const uint32_t* ap = a_base + mi * 16 * APAD + k0 + t;
            a[mi][0] = ap[0];
            a[mi][1] = ap[8 * APAD];
            a[mi][2] = ap[4];
            a[mi][3] = ap[8 * APAD + 4];
        }

        uint32_t b[8][2];
        const uint32_t* bp = b_base + (k0 + t) * BPAD;
        #pragma unroll
        for (int ni = 0; ni < 8; ni++) {
            b[ni][0] = bp[ni * 8];
            b[ni][1] = bp[ni * 8 + 4 * BPAD];
        }

        #pragma unroll
        for (int mi = 0; mi < 2; mi++)
            #pragma unroll
            for (int ni = 0; ni < 8; ni++)
                mma_tf32(c[mi][ni], a[mi][0], a[mi][1], a[mi][2], a[mi][3],
                         b[ni][0], b[ni][1]);
    }

    if (blockIdx.y == 0) {
        #pragma unroll
        for (int mi = 0; mi < 2; mi++) {
            int r_lo = row0 + warp_m * 32 + mi * 16 + g;
            #pragma unroll
            for (int ni = 0; ni < 8; ni++) {
                int col = warp_n * 64 + ni * 8 + 2 * t;
                if (r_lo < n_nodes)
                    *(float2*)&g_Q[(size_t)r_lo * HD + col] =
                        make_float2(c[mi][ni][0], c[mi][ni][1]);
                if (r_lo + 8 < n_nodes)
                    *(float2*)&g_Q[(size_t)(r_lo + 8) * HD + col] =
                        make_float2(c[mi][ni][2], c[mi][ni][3]);
            }
        }
    } else {
        __half* outh = (blockIdx.y == 1) ? g_Kh : g_Vh;
        #pragma unroll
        for (int mi = 0; mi < 2; mi++) {
            int r_lo = row0 + warp_m * 32 + mi * 16 + g;
            #pragma unroll
            for (int ni = 0; ni < 8; ni++) {
                int col = warp_n * 64 + ni * 8 + 2 * t;
                if (r_lo < n_nodes)
                    *(__half2*)&outh[(size_t)r_lo * HD + col] =
                        __floats2half2_rn(c[mi][ni][0], c[mi][ni][1]);
                if (r_lo + 8 < n_nodes)
                    *(__half2*)&outh[(size_t)(r_lo + 8) * HD + col] =
                        __floats2half2_rn(c[mi][ni][2], c[mi][ni][3]);
            }
        }
    }
}

// ---------------------------------------------------------------------------
// hist: dst-degree histogram, 4 edges/thread via int4 (MLP=4 on the REDGs).
// ---------------------------------------------------------------------------
__global__ __launch_bounds__(256)
void hist_kernel(const int* __restrict__ dst, int n_edges)
{
    int q = blockIdx.x * blockDim.x + threadIdx.x;   // quad index
    int e0 = q * 4;
    if (e0 + 4 <= n_edges) {
        int4 d4 = __ldg((const int4*)(dst + e0));
        atomicAdd(&g_deg[d4.x], 1);
        atomicAdd(&g_deg[d4.y], 1);
        atomicAdd(&g_deg[d4.z], 1);
        atomicAdd(&g_deg[d4.w], 1);
    } else {
        for (int e = e0; e < n_edges; e++)
            atomicAdd(&g_deg[__ldg(dst + e)], 1);
    }
}

// ---------------------------------------------------------------------------
// scan1: per-block exclusive scan of g_deg (1024/block), emits block sums,
// and ZEROES g_deg behind itself (restores the all-zero invariant).
// ---------------------------------------------------------------------------
__global__ __launch_bounds__(1024)
void scan1_kernel(int n)
{
    __shared__ int wsum[32];
    int tid  = threadIdx.x;
    int lane = tid & 31, wid = tid >> 5;
    int i = blockIdx.x * 1024 + tid;
    int v = 0;
    if (i < n) {
        v = g_deg[i];
        g_deg[i] = 0;                 // self-restore for the next call
    }
    int x = v;
    #pragma unroll
    for (int o = 1; o < 32; o <<= 1) {
        int y = __shfl_up_sync(0xffffffffu, x, o);
        if (lane >= o) x += y;
    }
    if (lane == 31) wsum[wid] = x;
    __syncthreads();
    if (wid == 0) {
        int w = wsum[lane];
        #pragma unroll
        for (int o = 1; o < 32; o <<= 1) {
            int y = __shfl_up_sync(0xffffffffu, w, o);
            if (lane >= o) w += y;
        }
        wsum[lane] = w;  // inclusive warp totals
    }
    __syncthreads();
    int woff = (wid > 0) ? wsum[wid - 1] : 0;
    if (i < n) g_scantmp[i] = woff + x - v;          // exclusive within block
    if (tid == 1023) g_bsums[blockIdx.x] = woff + x; // block total
}

// ---------------------------------------------------------------------------
// scan23: every block redundantly exclusive-scans the (<=64) block sums
// in-register, applies the offset, emits rowstart + cursor.
// ---------------------------------------------------------------------------
__global__ __launch_bounds__(1024)
void scan23_kernel(int n, int nb, int n_edges)
{
    __shared__ int boffs_s[64];
    __shared__ int wtot;
    int tid = threadIdx.x;
    if (tid < 64) {
        int lane = tid & 31;
        int v = (tid < nb) ? g_bsums[tid] : 0;
        int x = v;
        #pragma unroll
        for (int o = 1; o < 32; o <<= 1) {
            int y = __shfl_up_sync(0xffffffffu, x, o);
            if (lane >= o) x += y;
        }
        if (tid == 31) wtot = x;      // total of first warp's 32 sums
        __syncwarp();
        boffs_s[tid] = x - v;         // exclusive within each 32-group
    }
    __syncthreads();
    int i = blockIdx.x * 1024 + tid;
    int blk = i >> 10;
    int boff = boffs_s[blk] + ((blk >= 32) ? wtot : 0);
    if (i < n) {
        int r = g_scantmp[i] + boff;
        g_rowstart[i] = r;
        g_cursor[i]   = r;
    }
    if (i == n) g_rowstart[n] = n_edges;
}

// ---------------------------------------------------------------------------
// scatter: 4 edges/thread via int4 loads -> 4 independent ATOMGs in flight.
// ---------------------------------------------------------------------------
__global__ __launch_bounds__(256)
void scatter_kernel(const int* __restrict__ src, const int* __restrict__ dst,
                    int n_edges)
{
    int q = blockIdx.x * blockDim.x + threadIdx.x;
    int e0 = q * 4;
    if (e0 + 4 <= n_edges) {
        int4 s4 = __ldg((const int4*)(src + e0));
        int4 d4 = __ldg((const int4*)(dst + e0));
        int p0 = atomicAdd(&g_cursor[d4.x], 1);
        int p1 = atomicAdd(&g_cursor[d4.y], 1);
        int p2 = atomicAdd(&g_cursor[d4.z], 1);
        int p3 = atomicAdd(&g_cursor[d4.w], 1);
        g_src_sorted[p0] = s4.x;
        g_src_sorted[p1] = s4.y;
        g_src_sorted[p2] = s4.z;
        g_src_sorted[p3] = s4.w;
    } else {
        for (int e = e0; e < n_edges; e++) {
            int pos = atomicAdd(&g_cursor[__ldg(dst + e)], 1);
            g_src_sorted[pos] = __ldg(src + e);
        }
    }
}

// ---------------------------------------------------------------------------
// Aggregation: one warp per destination node, no atomics.
// Chunks of 8 edges -> 16 independent fp16 gathers per lane in flight.
// ---------------------------------------------------------------------------
__device__ __forceinline__ float4 h4_to_f4(uint2 u) {
    float2 a = __half22float2(*(__half2*)&u.x);
    float2 b = __half22float2(*(__half2*)&u.y);
    return make_float4(a.x, a.y, b.x, b.y);
}

__global__ __launch_bounds__(256)
void aggregate_kernel(float* __restrict__ out, int n_nodes)
{
    int gtid = blockIdx.x * blockDim.x + threadIdx.x;
    int d    = gtid >> 5;
    int lane = gtid & 31;
    if (d >= n_nodes) return;

    const float4* Q4 = (const float4*)g_Q;
    const uint2*  K2 = (const uint2*)g_Kh;   // node stride: 32 uint2 (128 half)
    const uint2*  V2 = (const uint2*)g_Vh;

    float4 q = __ldg(&Q4[(size_t)d * 32 + lane]);
    int beg = g_rowstart[d];
    int end = g_rowstart[d + 1];

    float4 acc = make_float4(0.f, 0.f, 0.f, 0.f);

    int e = beg;
    for (; e + 8 <= end; e += 8) {
        int s[8];
        #pragma unroll
        for (int j = 0; j < 8; j++) s[j] = __ldg(g_src_sorted + e + j);

        uint2 ku[8], vu[8];
        #pragma unroll
        for (int j = 0; j < 8; j++) ku[j] = __ldg(&K2[(size_t)s[j] * 32 + lane]);
        #pragma unroll
        for (int j = 0; j < 8; j++) vu[j] = __ldg(&V2[(size_t)s[j] * 32 + lane]);

        float p[8];
        #pragma unroll
        for (int j = 0; j < 8; j++) {
            float4 k = h4_to_f4(ku[j]);
            p[j] = k.x*q.x + k.y*q.y + k.z*q.z + k.w*q.w;
        }
        #pragma unroll
        for (int j = 0; j < 8; j++) p[j] += __shfl_xor_sync(0xffffffffu, p[j], 1);
        #pragma unroll
        for (int j = 0; j < 8; j++) p[j] += __shfl_xor_sync(0xffffffffu, p[j], 2);
        #pragma unroll
        for (int j = 0; j < 8; j++) {
            float pj = p[j] * 0.25f;             // 1/sqrt(16)
            float4 v = h4_to_f4(vu[j]);
            acc.x += pj * v.x; acc.y += pj * v.y;
            acc.z += pj * v.z; acc.w += pj * v.w;
        }
    }
    for (; e + 4 <= end; e += 4) {
        int s0 = __ldg(g_src_sorted + e);
        int s1 = __ldg(g_src_sorted + e + 1);
        int s2 = __ldg(g_src_sorted + e + 2);
        int s3 = __ldg(g_src_sorted + e + 3);

        uint2 ku0 = __ldg(&K2[(size_t)s0 * 32 + lane]);
        uint2 ku1 = __ldg(&K2[(size_t)s1 * 32 + lane]);
        uint2 ku2 = __ldg(&K2[(size_t)s2 * 32 + lane]);
        uint2 ku3 = __ldg(&K2[(size_t)s3 * 32 + lane]);
        uint2 vu0 = __ldg(&V2[(size_t)s0 * 32 + lane]);
        uint2 vu1 = __ldg(&V2[(size_t)s1 * 32 + lane]);
        uint2 vu2 = __ldg(&V2[(size_t)s2 * 32 + lane]);
        uint2 vu3 = __ldg(&V2[(size_t)s3 * 32 + lane]);

        float4 k0 = h4_to_f4(ku0), k1 = h4_to_f4(ku1);
        float4 k2 = h4_to_f4(ku2), k3 = h4_to_f4(ku3);

        float p0 = k0.x*q.x + k0.y*q.y + k0.z*q.z + k0.w*q.w;
        float p1 = k1.x*q.x + k1.y*q.y + k1.z*q.z + k1.w*q.w;
        float p2 = k2.x*q.x + k2.y*q.y + k2.z*q.z + k2.w*q.w;
        float p3 = k3.x*q.x + k3.y*q.y + k3.z*q.z + k3.w*q.w;

        p0 += __shfl_xor_sync(0xffffffffu, p0, 1);
        p1 += __shfl_xor_sync(0xffffffffu, p1, 1);
        p2 += __shfl_xor_sync(0xffffffffu, p2, 1);
        p3 += __shfl_xor_sync(0xffffffffu, p3, 1);
        p0 += __shfl_xor_sync(0xffffffffu, p0, 2);
        p1 += __shfl_xor_sync(0xffffffffu, p1, 2);
        p2 += __shfl_xor_sync(0xffffffffu, p2, 2);
        p3 += __shfl_xor_sync(0xffffffffu, p3, 2);
        p0 *= 0.25f; p1 *= 0.25f; p2 *= 0.25f; p3 *= 0.25f;

        float4 v0 = h4_to_f4(vu0), v1 = h4_to_f4(vu1);
        float4 v2 = h4_to_f4(vu2), v3 = h4_to_f4(vu3);

        acc.x += p0*v0.x + p1*v1.x + p2*v2.x + p3*v3.x;
        acc.y += p0*v0.y + p1*v1.y + p2*v2.y + p3*v3.y;
        acc.z += p0*v0.z + p1*v1.z + p2*v2.z + p3*v3.z;
        acc.w += p0*v0.w + p1*v1.w + p2*v2.w + p3*v3.w;
    }
    for (; e < end; e++) {
        int s = __ldg(g_src_sorted + e);
        float4 kv = h4_to_f4(__ldg(&K2[(size_t)s * 32 + lane]));
        float p = kv.x*q.x + kv.y*q.y + kv.z*q.z + kv.w*q.w;
        p += __shfl_xor_sync(0xffffffffu, p, 1);
        p += __shfl_xor_sync(0xffffffffu, p, 2);
        p *= 0.25f;
        float4 v = h4_to_f4(__ldg(&V2[(size_t)s * 32 + lane]));
        acc.x += p*v.x; acc.y += p*v.y; acc.z += p*v.z; acc.w += p*v.w;
    }

    *(float4*)&out[(size_t)d * HD + lane * 4] = acc;
}

// ---------------------------------------------------------------------------
// Launch. Two parallel branches inside the captured graph:
//   branch A (side stream): qkv_gemm
//   branch B (main stream): hist -> scan1 -> scan23 -> scatter
// joined before aggregate. Side stream + events are host-side resources
// (no device memory); created once, capture-recorded work identical per call.
// ---------------------------------------------------------------------------
extern "C" void kernel_launch(void* const* d_in, const int* in_sizes, int n_in,
                              void* d_out, int out_size)
{
    const float* h   = (const float*)d_in[0];
    const int*   src = (const int*)  d_in[1];
    const int*   dst = (const int*)  d_in[2];
    const float* Wq  = (const float*)d_in[3];
    const float* bq  = (const float*)d_in[4];
    const float* Wk  = (const float*)d_in[5];
    const float* bk  = (const float*)d_in[6];
    const float* Wv  = (const float*)d_in[7];
    const float* bv  = (const float*)d_in[8];
    float* out = (float*)d_out;

    int n_nodes = in_sizes[0] / IND;   // 50000
    int n_edges = in_sizes[1];         // 800000

    cudaFuncSetAttribute(qkv_gemm,
                         cudaFuncAttributeMaxDynamicSharedMemorySize,
                         GEMM_SMEM_BYTES);

    static cudaStream_t side = nullptr;
    static cudaEvent_t  evFork = nullptr, evGemm = nullptr;
    if (side == nullptr) {
        cudaStreamCreateWithFlags(&side, cudaStreamNonBlocking);
        cudaEventCreateWithFlags(&evFork, cudaEventDisableTiming);
        cudaEventCreateWithFlags(&evGemm, cudaEventDisableTiming);
    }

    // Fork: GEMM branch on side stream.
    cudaEventRecord(evFork, 0);
    cudaStreamWaitEvent(side, evFork, 0);
    dim3 ggrid((n_nodes + 127) / 128, 3);
    qkv_gemm<<<ggrid, 256, GEMM_SMEM_BYTES, side>>>(h, Wq, bq, Wk, bk, Wv, bv,
                                                    n_nodes);
    cudaEventRecord(evGemm, side);

    // CSR branch on main stream (concurrent with GEMM).
    int nquad = (n_edges + 3) / 4;
    int qb = (nquad + 255) / 256;
    hist_kernel<<<qb, 256>>>(dst, n_edges);

    int nb = (n_nodes + 1023) / 1024;              // 49 for N=50000
    scan1_kernel<<<nb, 1024>>>(n_nodes);
    int nb1 = (n_nodes + 1 + 1023) / 1024;
    scan23_kernel<<<nb1, 1024>>>(n_nodes, nb, n_edges);

    scatter_kernel<<<qb, 256>>>(src, dst, n_edges);

    // Join: aggregate needs both branches.
    cudaStreamWaitEvent(0, evGemm, 0);
    int ablocks = (n_nodes * 32 + 255) / 256;
    aggregate_kernel<<<ablocks, 256>>>(out, n_nodes);
}

// round 10
// speedup vs baseline: 1.2671x; 1.1079x over previous
#include <cuda_runtime.h>
#include <cuda_bf16.h>
#include <cuda_fp16.h>
#include <cstdint>

// Problem constants (shapes fixed by the reference)
#define NMAX   50000
#define EMAX   800000
#define IND    128        // IN_DIM
#define HD     128        // HEADS * D
#define HEADS  8
#define DDIM   16

// Scratch: Q fp32 (streamed once), K/V fp16 (gathered 16x each -> bytes matter)
__device__ float  g_Q[NMAX * HD];
__device__ __align__(16) __half g_Kh[NMAX * HD];
__device__ __align__(16) __half g_Vh[NMAX * HD];

// CSR-by-dst build scratch.
// INVARIANT: g_deg is all-zero at kernel_launch entry (BSS-zero initially;
// scan1 re-zeroes every element it reads, restoring the invariant each call).
__device__ int g_deg[NMAX];
__device__ int g_scantmp[NMAX];
__device__ int g_bsums[64];
__device__ int g_rowstart[NMAX + 1];
__device__ int g_cursor[NMAX];
__device__ int g_src_sorted[EMAX];

// ---------------------------------------------------------------------------
// QKV projection GEMM — fp16 MMA (m16n8k16, fp32 accumulate).
// fp16 and tf32 share a 10-bit mantissa -> identical input rounding to the
// previous tf32 version, but: half the mma count, half the operand smem
// traffic, half the smem footprint (68KB -> 3 CTAs/SM latency hiding).
//   A smem: [r][k] halfs, stride 136  (frag banks (4g+t)%32, conflict-free)
//   W smem: [n][k] halfs (transposed at staging), stride 136
// ---------------------------------------------------------------------------
#define PAD_H 136
#define GEMM_SMEM_BYTES (2 * 128 * PAD_H * 2)

__device__ __forceinline__ void mma_f16(float c[4],
                                        uint32_t a0, uint32_t a1,
                                        uint32_t a2, uint32_t a3,
                                        uint32_t b0, uint32_t b1) {
    asm volatile(
        "mma.sync.aligned.m16n8k16.row.col.f32.f16.f16.f32 "
        "{%0,%1,%2,%3}, {%4,%5,%6,%7}, {%8,%9}, {%0,%1,%2,%3};"
        : "+f"(c[0]), "+f"(c[1]), "+f"(c[2]), "+f"(c[3])
        : "r"(a0), "r"(a1), "r"(a2), "r"(a3), "r"(b0), "r"(b1));
}

__global__ __launch_bounds__(256)
void qkv_gemm(const float* __restrict__ h,
              const float* __restrict__ Wq, const float* __restrict__ bq,
              const float* __restrict__ Wk, const float* __restrict__ bk,
              const float* __restrict__ Wv, const float* __restrict__ bv,
              int n_nodes)
{
    extern __shared__ __half smemh[];
    __half* as = smemh;                  // as[r*PAD_H + k]
    __half* ws = smemh + 128 * PAD_H;    // ws[n*PAD_H + k]  (W transposed)

    const float* W;
    const float* bias;
    if (blockIdx.y == 0)      { W = Wq; bias = bq; }
    else if (blockIdx.y == 1) { W = Wk; bias = bk; }
    else                      { W = Wv; bias = bv; }

    const int row0 = blockIdx.x * 128;
    const int tid  = threadIdx.x;

    // Stage A (h tile): coalesced gmem, contiguous smem halfs.
    #pragma unroll
    for (int i = 0; i < 64; i++) {
        int lin = tid + i * 256;
        int r = lin >> 7;
        int k = lin & 127;
        float v = 0.0f;
        int gr = row0 + r;
        if (gr < n_nodes) v = h[gr * IND + k];
        as[r * PAD_H + k] = __float2half_rn(v);
    }
    // Stage W transposed: read W[k][n] coalesced, write ws[n][k].
    #pragma unroll
    for (int i = 0; i < 64; i++) {
        int lin = tid + i * 256;
        int k = lin >> 7;
        int n = lin & 127;
        ws[n * PAD_H + k] = __float2half_rn(W[k * HD + n]);
    }
    __syncthreads();

    const int warp   = tid >> 5;
    const int lane   = tid & 31;
    const int g      = lane >> 2;       // 0..7
    const int t      = lane & 3;        // 0..3
    const int warp_m = warp & 3;        // 0..3
    const int warp_n = warp >> 2;       // 0..1

    float c[2][8][4];
    #pragma unroll
    for (int ni = 0; ni < 8; ni++) {
        int col = warp_n * 64 + ni * 8 + 2 * t;
        float b0 = bias[col];
        float b1 = bias[col + 1];
        #pragma unroll
        for (int mi = 0; mi < 2; mi++) {
            c[mi][ni][0] = b0; c[mi][ni][1] = b1;
            c[mi][ni][2] = b0; c[mi][ni][3] = b1;
        }
    }

    const __half* a_base = as + (warp_m * 32 + g) * PAD_H + 2 * t;
    const __half* b_base = ws + (warp_n * 64 + g) * PAD_H + 2 * t;

    #pragma unroll
    for (int kk = 0; kk < 8; kk++) {
        const int k0 = kk * 16;

        // A fragments: a0={A[g][2t,2t+1]}, a1=row+8, a2=col+8, a3=both.
        uint32_t a[2][4];
        #pragma unroll
        for (int mi = 0; mi < 2; mi++) {
            const __half* ap = a_base + mi * 16 * PAD_H + k0;
            a[mi][0] = *(const uint32_t*)(ap);
            a[mi][1] = *(const uint32_t*)(ap + 8 * PAD_H);
            a[mi][2] = *(const uint32_t*)(ap + 8);
            a[mi][3] = *(const uint32_t*)(ap + 8 * PAD_H + 8);
        }

        // B fragments: b0={B[2t][g],B[2t+1][g]} = ws[n=g..][k0+2t..+1].
        uint32_t b[8][2];
        #pragma unroll
        for (int ni = 0; ni < 8; ni++) {
            const __half* bp = b_base + ni * 8 * PAD_H + k0;
            b[ni][0] = *(const uint32_t*)(bp);
            b[ni][1] = *(const uint32_t*)(bp + 8);
        }

        #pragma unroll
        for (int mi = 0; mi < 2; mi++)
            #pragma unroll
            for (int ni = 0; ni < 8; ni++)
                mma_f16(c[mi][ni], a[mi][0], a[mi][1], a[mi][2], a[mi][3],
                        b[ni][0], b[ni][1]);
    }

    if (blockIdx.y == 0) {
        #pragma unroll
        for (int mi = 0; mi < 2; mi++) {
            int r_lo = row0 + warp_m * 32 + mi * 16 + g;
            #pragma unroll
            for (int ni = 0; ni < 8; ni++) {
                int col = warp_n * 64 + ni * 8 + 2 * t;
                if (r_lo < n_nodes)
                    *(float2*)&g_Q[(size_t)r_lo * HD + col] =
                        make_float2(c[mi][ni][0], c[mi][ni][1]);
                if (r_lo + 8 < n_nodes)
                    *(float2*)&g_Q[(size_t)(r_lo + 8) * HD + col] =
                        make_float2(c[mi][ni][2], c[mi][ni][3]);
            }
        }
    } else {
        __half* outh = (blockIdx.y == 1) ? g_Kh : g_Vh;
        #pragma unroll
        for (int mi = 0; mi < 2; mi++) {
            int r_lo = row0 + warp_m * 32 + mi * 16 + g;
            #pragma unroll
            for (int ni = 0; ni < 8; ni++) {
                int col = warp_n * 64 + ni * 8 + 2 * t;
                if (r_lo < n_nodes)
                    *(__half2*)&outh[(size_t)r_lo * HD + col] =
                        __floats2half2_rn(c[mi][ni][0], c[mi][ni][1]);
                if (r_lo + 8 < n_nodes)
                    *(__half2*)&outh[(size_t)(r_lo + 8) * HD + col] =
                        __floats2half2_rn(c[mi][ni][2], c[mi][ni][3]);
            }
        }
    }
}

// ---------------------------------------------------------------------------
// hist: dst-degree histogram, 4 edges/thread via int4 (MLP=4 on the REDGs).
// ---------------------------------------------------------------------------
__global__ __launch_bounds__(256)
void hist_kernel(const int* __restrict__ dst, int n_edges)
{
    int q = blockIdx.x * blockDim.x + threadIdx.x;   // quad index
    int e0 = q * 4;
    if (e0 + 4 <= n_edges) {
        int4 d4 = __ldg((const int4*)(dst + e0));
        atomicAdd(&g_deg[d4.x], 1);
        atomicAdd(&g_deg[d4.y], 1);
        atomicAdd(&g_deg[d4.z], 1);
        atomicAdd(&g_deg[d4.w], 1);
    } else {
        for (int e = e0; e < n_edges; e++)
            atomicAdd(&g_deg[__ldg(dst + e)], 1);
    }
}

// ---------------------------------------------------------------------------
// scan1: per-block exclusive scan of g_deg (1024/block), emits block sums,
// and ZEROES g_deg behind itself (restores the all-zero invariant).
// ---------------------------------------------------------------------------
__global__ __launch_bounds__(1024)
void scan1_kernel(int n)
{
    __shared__ int wsum[32];
    int tid  = threadIdx.x;
    int lane = tid & 31, wid = tid >> 5;
    int i = blockIdx.x * 1024 + tid;
    int v = 0;
    if (i < n) {
        v = g_deg[i];
        g_deg[i] = 0;                 // self-restore for the next call
    }
    int x = v;
    #pragma unroll
    for (int o = 1; o < 32; o <<= 1) {
        int y = __shfl_up_sync(0xffffffffu, x, o);
        if (lane >= o) x += y;
    }
    if (lane == 31) wsum[wid] = x;
    __syncthreads();
    if (wid == 0) {
        int w = wsum[lane];
        #pragma unroll
        for (int o = 1; o < 32; o <<= 1) {
            int y = __shfl_up_sync(0xffffffffu, w, o);
            if (lane >= o) w += y;
        }
        wsum[lane] = w;  // inclusive warp totals
    }
    __syncthreads();
    int woff = (wid > 0) ? wsum[wid - 1] : 0;
    if (i < n) g_scantmp[i] = woff + x - v;          // exclusive within block
    if (tid == 1023) g_bsums[blockIdx.x] = woff + x; // block total
}

// ---------------------------------------------------------------------------
// scan23: every block redundantly exclusive-scans the (<=64) block sums
// in-register, applies the offset, emits rowstart + cursor.
// ---------------------------------------------------------------------------
__global__ __launch_bounds__(1024)
void scan23_kernel(int n, int nb, int n_edges)
{
    __shared__ int boffs_s[64];
    __shared__ int wtot;
    int tid = threadIdx.x;
    if (tid < 64) {
        int lane = tid & 31;
        int v = (tid < nb) ? g_bsums[tid] : 0;
        int x = v;
        #pragma unroll
        for (int o = 1; o < 32; o <<= 1) {
            int y = __shfl_up_sync(0xffffffffu, x, o);
            if (lane >= o) x += y;
        }
        if (tid == 31) wtot = x;      // total of first warp's 32 sums
        __syncwarp();
        boffs_s[tid] = x - v;         // exclusive within each 32-group
    }
    __syncthreads();
    int i = blockIdx.x * 1024 + tid;
    int blk = i >> 10;
    int boff = boffs_s[blk] + ((blk >= 32) ? wtot : 0);
    if (i < n) {
        int r = g_scantmp[i] + boff;
        g_rowstart[i] = r;
        g_cursor[i]   = r;
    }
    if (i == n) g_rowstart[n] = n_edges;
}

// ---------------------------------------------------------------------------
// scatter: 4 edges/thread via int4 loads -> 4 independent ATOMGs in flight.
// ---------------------------------------------------------------------------
__global__ __launch_bounds__(256)
void scatter_kernel(const int* __restrict__ src, const int* __restrict__ dst,
                    int n_edges)
{
    int q = blockIdx.x * blockDim.x + threadIdx.x;
    int e0 = q * 4;
    if (e0 + 4 <= n_edges) {
        int4 s4 = __ldg((const int4*)(src + e0));
        int4 d4 = __ldg((const int4*)(dst + e0));
        int p0 = atomicAdd(&g_cursor[d4.x], 1);
        int p1 = atomicAdd(&g_cursor[d4.y], 1);
        int p2 = atomicAdd(&g_cursor[d4.z], 1);
        int p3 = atomicAdd(&g_cursor[d4.w], 1);
        g_src_sorted[p0] = s4.x;
        g_src_sorted[p1] = s4.y;
        g_src_sorted[p2] = s4.z;
        g_src_sorted[p3] = s4.w;
    } else {
        for (int e = e0; e < n_edges; e++) {
            int pos = atomicAdd(&g_cursor[__ldg(dst + e)], 1);
            g_src_sorted[pos] = __ldg(src + e);
        }
    }
}

// ---------------------------------------------------------------------------
// Aggregation: one warp per destination node, no atomics.
// Chunks of 8 edges -> 16 independent fp16 gathers per lane in flight.
// ---------------------------------------------------------------------------
__device__ __forceinline__ float4 h4_to_f4(uint2 u) {
    float2 a = __half22float2(*(__half2*)&u.x);
    float2 b = __half22float2(*(__half2*)&u.y);
    return make_float4(a.x, a.y, b.x, b.y);
}

__global__ __launch_bounds__(256)
void aggregate_kernel(float* __restrict__ out, int n_nodes)
{
    int gtid = blockIdx.x * blockDim.x + threadIdx.x;
    int d    = gtid >> 5;
    int lane = gtid & 31;
    if (d >= n_nodes) return;

    const float4* Q4 = (const float4*)g_Q;
    const uint2*  K2 = (const uint2*)g_Kh;   // node stride: 32 uint2 (128 half)
    const uint2*  V2 = (const uint2*)g_Vh;

    float4 q = __ldg(&Q4[(size_t)d * 32 + lane]);
    int beg = g_rowstart[d];
    int end = g_rowstart[d + 1];

    float4 acc = make_float4(0.f, 0.f, 0.f, 0.f);

    int e = beg;
    for (; e + 8 <= end; e += 8) {
        int s[8];
        #pragma unroll
        for (int j = 0; j < 8; j++) s[j] = __ldg(g_src_sorted + e + j);

        uint2 ku[8], vu[8];
        #pragma unroll
        for (int j = 0; j < 8; j++) ku[j] = __ldg(&K2[(size_t)s[j] * 32 + lane]);
        #pragma unroll
        for (int j = 0; j < 8; j++) vu[j] = __ldg(&V2[(size_t)s[j] * 32 + lane]);

        float p[8];
        #pragma unroll
        for (int j = 0; j < 8; j++) {
            float4 k = h4_to_f4(ku[j]);
            p[j] = k.x*q.x + k.y*q.y + k.z*q.z + k.w*q.w;
        }
        #pragma unroll
        for (int j = 0; j < 8; j++) p[j] += __shfl_xor_sync(0xffffffffu, p[j], 1);
        #pragma unroll
        for (int j = 0; j < 8; j++) p[j] += __shfl_xor_sync(0xffffffffu, p[j], 2);
        #pragma unroll
        for (int j = 0; j < 8; j++) {
            float pj = p[j] * 0.25f;             // 1/sqrt(16)
            float4 v = h4_to_f4(vu[j]);
            acc.x += pj * v.x; acc.y += pj * v.y;
            acc.z += pj * v.z; acc.w += pj * v.w;
        }
    }
    for (; e + 4 <= end; e += 4) {
        int s0 = __ldg(g_src_sorted + e);
        int s1 = __ldg(g_src_sorted + e + 1);
        int s2 = __ldg(g_src_sorted + e + 2);
        int s3 = __ldg(g_src_sorted + e + 3);

        uint2 ku0 = __ldg(&K2[(size_t)s0 * 32 + lane]);
        uint2 ku1 = __ldg(&K2[(size_t)s1 * 32 + lane]);
        uint2 ku2 = __ldg(&K2[(size_t)s2 * 32 + lane]);
        uint2 ku3 = __ldg(&K2[(size_t)s3 * 32 + lane]);
        uint2 vu0 = __ldg(&V2[(size_t)s0 * 32 + lane]);
        uint2 vu1 = __ldg(&V2[(size_t)s1 * 32 + lane]);
        uint2 vu2 = __ldg(&V2[(size_t)s2 * 32 + lane]);
        uint2 vu3 = __ldg(&V2[(size_t)s3 * 32 + lane]);

        float4 k0 = h4_to_f4(ku0), k1 = h4_to_f4(ku1);
        float4 k2 = h4_to_f4(ku2), k3 = h4_to_f4(ku3);

        float p0 = k0.x*q.x + k0.y*q.y + k0.z*q.z + k0.w*q.w;
        float p1 = k1.x*q.x + k1.y*q.y + k1.z*q.z + k1.w*q.w;
        float p2 = k2.x*q.x + k2.y*q.y + k2.z*q.z + k2.w*q.w;
        float p3 = k3.x*q.x + k3.y*q.y + k3.z*q.z + k3.w*q.w;

        p0 += __shfl_xor_sync(0xffffffffu, p0, 1);
        p1 += __shfl_xor_sync(0xffffffffu, p1, 1);
        p2 += __shfl_xor_sync(0xffffffffu, p2, 1);
        p3 += __shfl_xor_sync(0xffffffffu, p3, 1);
        p0 += __shfl_xor_sync(0xffffffffu, p0, 2);
        p1 += __shfl_xor_sync(0xffffffffu, p1, 2);
        p2 += __shfl_xor_sync(0xffffffffu, p2, 2);
        p3 += __shfl_xor_sync(0xffffffffu, p3, 2);
        p0 *= 0.25f; p1 *= 0.25f; p2 *= 0.25f; p3 *= 0.25f;

        float4 v0 = h4_to_f4(vu0), v1 = h4_to_f4(vu1);
        float4 v2 = h4_to_f4(vu2), v3 = h4_to_f4(vu3);

        acc.x += p0*v0.x + p1*v1.x + p2*v2.x + p3*v3.x;
        acc.y += p0*v0.y + p1*v1.y + p2*v2.y + p3*v3.y;
        acc.z += p0*v0.z + p1*v1.z + p2*v2.z + p3*v3.z;
        acc.w += p0*v0.w + p1*v1.w + p2*v2.w + p3*v3.w;
    }
    for (; e < end; e++) {
        int s = __ldg(g_src_sorted + e);
        float4 kv = h4_to_f4(__ldg(&K2[(size_t)s * 32 + lane]));
        float p = kv.x*q.x + kv.y*q.y + kv.z*q.z + kv.w*q.w;
        p += __shfl_xor_sync(0xffffffffu, p, 1);
        p += __shfl_xor_sync(0xffffffffu, p, 2);
        p *= 0.25f;
        float4 v = h4_to_f4(__ldg(&V2[(size_t)s * 32 + lane]));
        acc.x += p*v.x; acc.y += p*v.y; acc.z += p*v.z; acc.w += p*v.w;
    }

    *(float4*)&out[(size_t)d * HD + lane * 4] = acc;
}

// ---------------------------------------------------------------------------
// Launch. Two parallel branches inside the captured graph:
//   branch A (side stream): qkv_gemm
//   branch B (main stream): hist -> scan1 -> scan23 -> scatter
// joined before aggregate.
// ---------------------------------------------------------------------------
extern "C" void kernel_launch(void* const* d_in, const int* in_sizes, int n_in,
                              void* d_out, int out_size)
{
    const float* h   = (const float*)d_in[0];
    const int*   src = (const int*)  d_in[1];
    const int*   dst = (const int*)  d_in[2];
    const float* Wq  = (const float*)d_in[3];
    const float* bq  = (const float*)d_in[4];
    const float* Wk  = (const float*)d_in[5];
    const float* bk  = (const float*)d_in[6];
    const float* Wv  = (const float*)d_in[7];
    const float* bv  = (const float*)d_in[8];
    float* out = (float*)d_out;

    int n_nodes = in_sizes[0] / IND;   // 50000
    int n_edges = in_sizes[1];         // 800000

    cudaFuncSetAttribute(qkv_gemm,
                         cudaFuncAttributeMaxDynamicSharedMemorySize,
                         GEMM_SMEM_BYTES);

    static cudaStream_t side = nullptr;
    static cudaEvent_t  evFork = nullptr, evGemm = nullptr;
    if (side == nullptr) {
        cudaStreamCreateWithFlags(&side, cudaStreamNonBlocking);
        cudaEventCreateWithFlags(&evFork, cudaEventDisableTiming);
        cudaEventCreateWithFlags(&evGemm, cudaEventDisableTiming);
    }

    // Fork: GEMM branch on side stream.
    cudaEventRecord(evFork, 0);
    cudaStreamWaitEvent(side, evFork, 0);
    dim3 ggrid((n_nodes + 127) / 128, 3);
    qkv_gemm<<<ggrid, 256, GEMM_SMEM_BYTES, side>>>(h, Wq, bq, Wk, bk, Wv, bv,
                                                    n_nodes);
    cudaEventRecord(evGemm, side);

    // CSR branch on main stream (concurrent with GEMM).
    int nquad = (n_edges + 3) / 4;
    int qb = (nquad + 255) / 256;
    hist_kernel<<<qb, 256>>>(dst, n_edges);

    int nb = (n_nodes + 1023) / 1024;              // 49 for N=50000
    scan1_kernel<<<nb, 1024>>>(n_nodes);
    int nb1 = (n_nodes + 1 + 1023) / 1024;
    scan23_kernel<<<nb1, 1024>>>(n_nodes, nb, n_edges);

    scatter_kernel<<<qb, 256>>>(src, dst, n_edges);

    // Join: aggregate needs both branches.
    cudaStreamWaitEvent(0, evGemm, 0);
    int ablocks = (n_nodes * 32 + 255) / 256;
    aggregate_kernel<<<ablocks, 256>>>(out, n_nodes);
}

// round 12
// speedup vs baseline: 1.3288x; 1.0487x over previous
#include <cuda_runtime.h>
#include <cuda_bf16.h>
#include <cuda_fp16.h>
#include <cstdint>

// Problem constants (shapes fixed by the reference)
#define NMAX   50000
#define EMAX   800000
#define IND    128        // IN_DIM
#define HD     128        // HEADS * D
#define HEADS  8
#define DDIM   16

// Scratch: Q fp32 (streamed once). K and V interleaved fp16:
//   g_KV[node*256 + g*8 + 0..3] = K dims 4g..4g+3
//   g_KV[node*256 + g*8 + 4..7] = V dims 4g..4g+3     (g = 0..31)
// One 16B load per (edge, lane) fetches both K and V chunks.
// Node stride = 256 halves = 512 bytes = 32 uint4.
__device__ float  g_Q[NMAX * HD];
__device__ __align__(16) __half g_KV[NMAX * HD * 2];

// CSR-by-dst build scratch.
// INVARIANT: g_deg is all-zero at kernel_launch entry (BSS-zero initially;
// scan1 re-zeroes every element it reads, restoring the invariant each call).
__device__ int g_deg[NMAX];
__device__ int g_scantmp[NMAX];
__device__ int g_bsums[64];
__device__ int g_rowstart[NMAX + 1];
__device__ int g_cursor[NMAX];
__device__ int g_src_sorted[EMAX];

// ---------------------------------------------------------------------------
// QKV projection GEMM — fp16 MMA (m16n8k16, fp32 accumulate).
//   A smem: [r][k] halfs, stride 136; W smem: [n][k] halfs (transposed).
// Q written fp32; K/V written fp16 into the interleaved g_KV layout.
// ---------------------------------------------------------------------------
#define PAD_H 136
#define GEMM_SMEM_BYTES (2 * 128 * PAD_H * 2)

__device__ __forceinline__ void mma_f16(float c[4],
                                        uint32_t a0, uint32_t a1,
                                        uint32_t a2, uint32_t a3,
                                        uint32_t b0, uint32_t b1) {
    asm volatile(
        "mma.sync.aligned.m16n8k16.row.col.f32.f16.f16.f32 "
        "{%0,%1,%2,%3}, {%4,%5,%6,%7}, {%8,%9}, {%0,%1,%2,%3};"
        : "+f"(c[0]), "+f"(c[1]), "+f"(c[2]), "+f"(c[3])
        : "r"(a0), "r"(a1), "r"(a2), "r"(a3), "r"(b0), "r"(b1));
}

__global__ __launch_bounds__(256)
void qkv_gemm(const float* __restrict__ h,
              const float* __restrict__ Wq, const float* __restrict__ bq,
              const float* __restrict__ Wk, const float* __restrict__ bk,
              const float* __restrict__ Wv, const float* __restrict__ bv,
              int n_nodes)
{
    extern __shared__ __half smemh[];
    __half* as = smemh;                  // as[r*PAD_H + k]
    __half* ws = smemh + 128 * PAD_H;    // ws[n*PAD_H + k]  (W transposed)

    const float* W;
    const float* bias;
    if (blockIdx.y == 0)      { W = Wq; bias = bq; }
    else if (blockIdx.y == 1) { W = Wk; bias = bk; }
    else                      { W = Wv; bias = bv; }

    const int row0 = blockIdx.x * 128;
    const int tid  = threadIdx.x;

    #pragma unroll
    for (int i = 0; i < 64; i++) {
        int lin = tid + i * 256;
        int r = lin >> 7;
        int k = lin & 127;
        float v = 0.0f;
        int gr = row0 + r;
        if (gr < n_nodes) v = h[gr * IND + k];
        as[r * PAD_H + k] = __float2half_rn(v);
    }
    #pragma unroll
    for (int i = 0; i < 64; i++) {
        int lin = tid + i * 256;
        int k = lin >> 7;
        int n = lin & 127;
        ws[n * PAD_H + k] = __float2half_rn(W[k * HD + n]);
    }
    __syncthreads();

    const int warp   = tid >> 5;
    const int lane   = tid & 31;
    const int g      = lane >> 2;       // 0..7
    const int t      = lane & 3;        // 0..3
    const int warp_m = warp & 3;        // 0..3
    const int warp_n = warp >> 2;       // 0..1

    float c[2][8][4];
    #pragma unroll
    for (int ni = 0; ni < 8; ni++) {
        int col = warp_n * 64 + ni * 8 + 2 * t;
        float b0 = bias[col];
        float b1 = bias[col + 1];
        #pragma unroll
        for (int mi = 0; mi < 2; mi++) {
            c[mi][ni][0] = b0; c[mi][ni][1] = b1;
            c[mi][ni][2] = b0; c[mi][ni][3] = b1;
        }
    }

    const __half* a_base = as + (warp_m * 32 + g) * PAD_H + 2 * t;
    const __half* b_base = ws + (warp_n * 64 + g) * PAD_H + 2 * t;

    #pragma unroll
    for (int kk = 0; kk < 8; kk++) {
        const int k0 = kk * 16;

        uint32_t a[2][4];
        #pragma unroll
        for (int mi = 0; mi < 2; mi++) {
            const __half* ap = a_base + mi * 16 * PAD_H + k0;
            a[mi][0] = *(const uint32_t*)(ap);
            a[mi][1] = *(const uint32_t*)(ap + 8 * PAD_H);
            a[mi][2] = *(const uint32_t*)(ap + 8);
            a[mi][3] = *(const uint32_t*)(ap + 8 * PAD_H + 8);
        }

        uint32_t b[8][2];
        #pragma unroll
        for (int ni = 0; ni < 8; ni++) {
            const __half* bp = b_base + ni * 8 * PAD_H + k0;
            b[ni][0] = *(const uint32_t*)(bp);
            b[ni][1] = *(const uint32_t*)(bp + 8);
        }

        #pragma unroll
        for (int mi = 0; mi < 2; mi++)
            #pragma unroll
            for (int ni = 0; ni < 8; ni++)
                mma_f16(c[mi][ni], a[mi][0], a[mi][1], a[mi][2], a[mi][3],
                        b[ni][0], b[ni][1]);
    }

    if (blockIdx.y == 0) {
        #pragma unroll
        for (int mi = 0; mi < 2; mi++) {
            int r_lo = row0 + warp_m * 32 + mi * 16 + g;
            #pragma unroll
            for (int ni = 0; ni < 8; ni++) {
                int col = warp_n * 64 + ni * 8 + 2 * t;
                if (r_lo < n_nodes)
                    *(float2*)&g_Q[(size_t)r_lo * HD + col] =
                        make_float2(c[mi][ni][0], c[mi][ni][1]);
                if (r_lo + 8 < n_nodes)
                    *(float2*)&g_Q[(size_t)(r_lo + 8) * HD + col] =
                        make_float2(c[mi][ni][2], c[mi][ni][3]);
            }
        }
    } else {
        // Interleaved KV layout: K at group-offset 0..3, V at 4..7.
        const int kvofs = (blockIdx.y == 1) ? 0 : 4;
        #pragma unroll
        for (int mi = 0; mi < 2; mi++) {
            int r_lo = row0 + warp_m * 32 + mi * 16 + g;
            #pragma unroll
            for (int ni = 0; ni < 8; ni++) {
                int col = warp_n * 64 + ni * 8 + 2 * t;      // even
                int ofs = (col >> 2) * 8 + (col & 3) + kvofs; // contiguous pair
                if (r_lo < n_nodes)
                    *(__half2*)&g_KV[(size_t)r_lo * 256 + ofs] =
                        __floats2half2_rn(c[mi][ni][0], c[mi][ni][1]);
                if (r_lo + 8 < n_nodes)
                    *(__half2*)&g_KV[(size_t)(r_lo + 8) * 256 + ofs] =
                        __floats2half2_rn(c[mi][ni][2], c[mi][ni][3]);
            }
        }
    }
}

// ---------------------------------------------------------------------------
// hist: dst-degree histogram, 4 edges/thread via int4 (MLP=4 on the REDGs).
// ---------------------------------------------------------------------------
__global__ __launch_bounds__(256)
void hist_kernel(const int* __restrict__ dst, int n_edges)
{
    int q = blockIdx.x * blockDim.x + threadIdx.x;   // quad index
    int e0 = q * 4;
    if (e0 + 4 <= n_edges) {
        int4 d4 = __ldg((const int4*)(dst + e0));
        atomicAdd(&g_deg[d4.x], 1);
        atomicAdd(&g_deg[d4.y], 1);
        atomicAdd(&g_deg[d4.z], 1);
        atomicAdd(&g_deg[d4.w], 1);
    } else {
        for (int e = e0; e < n_edges; e++)
            atomicAdd(&g_deg[__ldg(dst + e)], 1);
    }
}

// ---------------------------------------------------------------------------
// scan1: per-block exclusive scan of g_deg (1024/block), emits block sums,
// and ZEROES g_deg behind itself (restores the all-zero invariant).
// ---------------------------------------------------------------------------
__global__ __launch_bounds__(1024)
void scan1_kernel(int n)
{
    __shared__ int wsum[32];
    int tid  = threadIdx.x;
    int lane = tid & 31, wid = tid >> 5;
    int i = blockIdx.x * 1024 + tid;
    int v = 0;
    if (i < n) {
        v = g_deg[i];
        g_deg[i] = 0;                 // self-restore for the next call
    }
    int x = v;
    #pragma unroll
    for (int o = 1; o < 32; o <<= 1) {
        int y = __shfl_up_sync(0xffffffffu, x, o);
        if (lane >= o) x += y;
    }
    if (lane == 31) wsum[wid] = x;
    __syncthreads();
    if (wid == 0) {
        int w = wsum[lane];
        #pragma unroll
        for (int o = 1; o < 32; o <<= 1) {
            int y = __shfl_up_sync(0xffffffffu, w, o);
            if (lane >= o) w += y;
        }
        wsum[lane] = w;  // inclusive warp totals
    }
    __syncthreads();
    int woff = (wid > 0) ? wsum[wid - 1] : 0;
    if (i < n) g_scantmp[i] = woff + x - v;          // exclusive within block
    if (tid == 1023) g_bsums[blockIdx.x] = woff + x; // block total
}

// ---------------------------------------------------------------------------
// scan23: every block redundantly exclusive-scans the (<=64) block sums
// in-register, applies the offset, emits rowstart + cursor.
// ---------------------------------------------------------------------------
__global__ __launch_bounds__(1024)
void scan23_kernel(int n, int nb, int n_edges)
{
    __shared__ int boffs_s[64];
    __shared__ int wtot;
    int tid = threadIdx.x;
    if (tid < 64) {
        int lane = tid & 31;
        int v = (tid < nb) ? g_bsums[tid] : 0;
        int x = v;
        #pragma unroll
        for (int o = 1; o < 32; o <<= 1) {
            int y = __shfl_up_sync(0xffffffffu, x, o);
            if (lane >= o) x += y;
        }
        if (tid == 31) wtot = x;      // total of first warp's 32 sums
        __syncwarp();
        boffs_s[tid] = x - v;         // exclusive within each 32-group
    }
    __syncthreads();
    int i = blockIdx.x * 1024 + tid;
    int blk = i >> 10;
    int boff = boffs_s[blk] + ((blk >= 32) ? wtot : 0);
    if (i < n) {
        int r = g_scantmp[i] + boff;
        g_rowstart[i] = r;
        g_cursor[i]   = r;
    }
    if (i == n) g_rowstart[n] = n_edges;
}

// ---------------------------------------------------------------------------
// scatter: 4 edges/thread via int4 loads -> 4 independent ATOMGs in flight.
// ---------------------------------------------------------------------------
__global__ __launch_bounds__(256)
void scatter_kernel(const int* __restrict__ src, const int* __restrict__ dst,
                    int n_edges)
{
    int q = blockIdx.x * blockDim.x + threadIdx.x;
    int e0 = q * 4;
    if (e0 + 4 <= n_edges) {
        int4 s4 = __ldg((const int4*)(src + e0));
        int4 d4 = __ldg((const int4*)(dst + e0));
        int p0 = atomicAdd(&g_cursor[d4.x], 1);
        int p1 = atomicAdd(&g_cursor[d4.y], 1);
        int p2 = atomicAdd(&g_cursor[d4.z], 1);
        int p3 = atomicAdd(&g_cursor[d4.w], 1);
        g_src_sorted[p0] = s4.x;
        g_src_sorted[p1] = s4.y;
        g_src_sorted[p2] = s4.z;
        g_src_sorted[p3] = s4.w;
    } else {
        for (int e = e0; e < n_edges; e++) {
            int pos = atomicAdd(&g_cursor[__ldg(dst + e)], 1);
            g_src_sorted[pos] = __ldg(src + e);
        }
    }
}

// ---------------------------------------------------------------------------
// Aggregation: one warp per destination node, no atomics.
// ONE uint4 (16B) gather per (edge, lane) fetches both the K and V chunk
// (interleaved layout) -> half the load instructions / latency chains of the
// split-array version. Chunks of 8 edges -> 8 independent LDG.128 in flight.
// Node stride in uint4 units: 32 (256 halves).
// ---------------------------------------------------------------------------
__device__ __forceinline__ float4 h4lo(uint4 u) {   // K halves 0..3
    float2 a = __half22float2(*(__half2*)&u.x);
    float2 b = __half22float2(*(__half2*)&u.y);
    return make_float4(a.x, a.y, b.x, b.y);
}
__device__ __forceinline__ float4 h4hi(uint4 u) {   // V halves 4..7
    float2 a = __half22float2(*(__half2*)&u.z);
    float2 b = __half22float2(*(__half2*)&u.w);
    return make_float4(a.x, a.y, b.x, b.y);
}

__global__ __launch_bounds__(256)
void aggregate_kernel(float* __restrict__ out, int n_nodes)
{
    int gtid = blockIdx.x * blockDim.x + threadIdx.x;
    int d    = gtid >> 5;
    int lane = gtid & 31;
    if (d >= n_nodes) return;

    const float4* Q4  = (const float4*)g_Q;
    const uint4*  KV4 = (const uint4*)g_KV;  // node stride: 32 uint4 (256 half)

    float4 q = __ldg(&Q4[(size_t)d * 32 + lane]);
    int beg = g_rowstart[d];
    int end = g_rowstart[d + 1];

    float4 acc = make_float4(0.f, 0.f, 0.f, 0.f);

    int e = beg;
    for (; e + 8 <= end; e += 8) {
        int s[8];
        #pragma unroll
        for (int j = 0; j < 8; j++) s[j] = __ldg(g_src_sorted + e + j);

        uint4 kv[8];
        #pragma unroll
        for (int j = 0; j < 8; j++)
            kv[j] = __ldg(&KV4[(size_t)s[j] * 32 + lane]);

        float p[8];
        #pragma unroll
        for (int j = 0; j < 8; j++) {
            float4 k = h4lo(kv[j]);
            p[j] = k.x*q.x + k.y*q.y + k.z*q.z + k.w*q.w;
        }
        #pragma unroll
        for (int j = 0; j < 8; j++) p[j] += __shfl_xor_sync(0xffffffffu, p[j], 1);
        #pragma unroll
        for (int j = 0; j < 8; j++) p[j] += __shfl_xor_sync(0xffffffffu, p[j], 2);
        #pragma unroll
        for (int j = 0; j < 8; j++) {
            float pj = p[j] * 0.25f;             // 1/sqrt(16)
            float4 v = h4hi(kv[j]);
            acc.x += pj * v.x; acc.y += pj * v.y;
            acc.z += pj * v.z; acc.w += pj * v.w;
        }
    }
    for (; e + 4 <= end; e += 4) {
        int s0 = __ldg(g_src_sorted + e);
        int s1 = __ldg(g_src_sorted + e + 1);
        int s2 = __ldg(g_src_sorted + e + 2);
        int s3 = __ldg(g_src_sorted + e + 3);

        uint4 kv0 = __ldg(&KV4[(size_t)s0 * 32 + lane]);
        uint4 kv1 = __ldg(&KV4[(size_t)s1 * 32 + lane]);
        uint4 kv2 = __ldg(&KV4[(size_t)s2 * 32 + lane]);
        uint4 kv3 = __ldg(&KV4[(size_t)s3 * 32 + lane]);

        float4 k0 = h4lo(kv0), k1 = h4lo(kv1), k2 = h4lo(kv2), k3 = h4lo(kv3);

        float p0 = k0.x*q.x + k0.y*q.y + k0.z*q.z + k0.w*q.w;
        float p1 = k1.x*q.x + k1.y*q.y + k1.z*q.z + k1.w*q.w;
        float p2 = k2.x*q.x + k2.y*q.y + k2.z*q.z + k2.w*q.w;
        float p3 = k3.x*q.x + k3.y*q.y + k3.z*q.z + k3.w*q.w;

        p0 += __shfl_xor_sync(0xffffffffu, p0, 1);
        p1 += __shfl_xor_sync(0xffffffffu, p1, 1);
        p2 += __shfl_xor_sync(0xffffffffu, p2, 1);
        p3 += __shfl_xor_sync(0xffffffffu, p3, 1);
        p0 += __shfl_xor_sync(0xffffffffu, p0, 2);
        p1 += __shfl_xor_sync(0xffffffffu, p1, 2);
        p2 += __shfl_xor_sync(0xffffffffu, p2, 2);
        p3 += __shfl_xor_sync(0xffffffffu, p3, 2);
        p0 *= 0.25f; p1 *= 0.25f; p2 *= 0.25f; p3 *= 0.25f;

        float4 v0 = h4hi(kv0), v1 = h4hi(kv1), v2 = h4hi(kv2), v3 = h4hi(kv3);

        acc.x += p0*v0.x + p1*v1.x + p2*v2.x + p3*v3.x;
        acc.y += p0*v0.y + p1*v1.y + p2*v2.y + p3*v3.y;
        acc.z += p0*v0.z + p1*v1.z + p2*v2.z + p3*v3.z;
        acc.w += p0*v0.w + p1*v1.w + p2*v2.w + p3*v3.w;
    }
    for (; e < end; e++) {
        int s = __ldg(g_src_sorted + e);
        uint4 kv = __ldg(&KV4[(size_t)s * 32 + lane]);
        float4 k = h4lo(kv);
        float p = k.x*q.x + k.y*q.y + k.z*q.z + k.w*q.w;
        p += __shfl_xor_sync(0xffffffffu, p, 1);
        p += __shfl_xor_sync(0xffffffffu, p, 2);
        p *= 0.25f;
        float4 v = h4hi(kv);
        acc.x += p*v.x; acc.y += p*v.y; acc.z += p*v.z; acc.w += p*v.w;
    }

    *(float4*)&out[(size_t)d * HD + lane * 4] = acc;
}

// ---------------------------------------------------------------------------
// Launch. Two parallel branches inside the captured graph:
//   branch A (side stream): qkv_gemm
//   branch B (main stream): hist -> scan1 -> scan23 -> scatter
// joined before aggregate.
// ---------------------------------------------------------------------------
extern "C" void kernel_launch(void* const* d_in, const int* in_sizes, int n_in,
                              void* d_out, int out_size)
{
    const float* h   = (const float*)d_in[0];
    const int*   src = (const int*)  d_in[1];
    const int*   dst = (const int*)  d_in[2];
    const float* Wq  = (const float*)d_in[3];
    const float* bq  = (const float*)d_in[4];
    const float* Wk  = (const float*)d_in[5];
    const float* bk  = (const float*)d_in[6];
    const float* Wv  = (const float*)d_in[7];
    const float* bv  = (const float*)d_in[8];
    float* out = (float*)d_out;

    int n_nodes = in_sizes[0] / IND;   // 50000
    int n_edges = in_sizes[1];         // 800000

    cudaFuncSetAttribute(qkv_gemm,
                         cudaFuncAttributeMaxDynamicSharedMemorySize,
                         GEMM_SMEM_BYTES);

    static cudaStream_t side = nullptr;
    static cudaEvent_t  evFork = nullptr, evGemm = nullptr;
    if (side == nullptr) {
        cudaStreamCreateWithFlags(&side, cudaStreamNonBlocking);
        cudaEventCreateWithFlags(&evFork, cudaEventDisableTiming);
        cudaEventCreateWithFlags(&evGemm, cudaEventDisableTiming);
    }

    // Fork: GEMM branch on side stream.
    cudaEventRecord(evFork, 0);
    cudaStreamWaitEvent(side, evFork, 0);
    dim3 ggrid((n_nodes + 127) / 128, 3);
    qkv_gemm<<<ggrid, 256, GEMM_SMEM_BYTES, side>>>(h, Wq, bq, Wk, bk, Wv, bv,
                                                    n_nodes);
    cudaEventRecord(evGemm, side);

    // CSR branch on main stream (concurrent with GEMM).
    int nquad = (n_edges + 3) / 4;
    int qb = (nquad + 255) / 256;
    hist_kernel<<<qb, 256>>>(dst, n_edges);

    int nb = (n_nodes + 1023) / 1024;              // 49 for N=50000
    scan1_kernel<<<nb, 1024>>>(n_nodes);
    int nb1 = (n_nodes + 1 + 1023) / 1024;
    scan23_kernel<<<nb1, 1024>>>(n_nodes, nb, n_edges);

    scatter_kernel<<<qb, 256>>>(src, dst, n_edges);

    // Join: aggregate needs both branches.
    cudaStreamWaitEvent(0, evGemm, 0);
    int ablocks = (n_nodes * 32 + 255) / 256;
    aggregate_kernel<<<ablocks, 256>>>(out, n_nodes);
}

// round 14
// speedup vs baseline: 1.3957x; 1.0503x over previous
#include <cuda_runtime.h>
#include <cuda_bf16.h>
#include <cuda_fp16.h>
#include <cstdint>

// Problem constants (shapes fixed by the reference)
#define NMAX   50000
#define EMAX   800000
#define IND    128        // IN_DIM
#define HD     128        // HEADS * D
#define HEADS  8
#define DDIM   16

// Scratch: Q fp32 (streamed once). K and V interleaved fp16:
//   g_KV[node*256 + g*8 + 0..3] = K dims 4g..4g+3
//   g_KV[node*256 + g*8 + 4..7] = V dims 4g..4g+3     (g = 0..31)
// One 16B load per (edge, lane) fetches both K and V chunks.
// Node stride = 256 halves = 512 bytes = 32 uint4.
__device__ float  g_Q[NMAX * HD];
__device__ __align__(16) __half g_KV[NMAX * HD * 2];

// CSR-by-dst build scratch.
// INVARIANT: g_deg is all-zero at kernel_launch entry (BSS-zero initially;
// scan1 re-zeroes every element it reads, restoring the invariant each call).
__device__ int g_deg[NMAX];
__device__ int g_scantmp[NMAX];
__device__ int g_bsums[64];
__device__ int g_rowstart[NMAX + 1];
__device__ int g_cursor[NMAX];
__device__ int g_src_sorted[EMAX];

// ---------------------------------------------------------------------------
// FUSED QKV projection GEMM — fp16 MMA (m16n8k16, fp32 accumulate).
// One CTA per 128-row tile stages the h tile ONCE, then loops over the three
// weight matrices (re-staging only the 34KB W tile between phases).
// vs the 3-way split kernel: h read 1x instead of 3x (103MB -> 52MB traffic),
// 1/3 the CTAs, 3x staging amortization. Same MMA work.
//   A smem: [r][k] halfs, stride 136; W smem: [n][k] halfs (transposed).
// ---------------------------------------------------------------------------
#define PAD_H 136
#define GEMM_SMEM_BYTES (2 * 128 * PAD_H * 2)

__device__ __forceinline__ void mma_f16(float c[4],
                                        uint32_t a0, uint32_t a1,
                                        uint32_t a2, uint32_t a3,
                                        uint32_t b0, uint32_t b1) {
    asm volatile(
        "mma.sync.aligned.m16n8k16.row.col.f32.f16.f16.f32 "
        "{%0,%1,%2,%3}, {%4,%5,%6,%7}, {%8,%9}, {%0,%1,%2,%3};"
        : "+f"(c[0]), "+f"(c[1]), "+f"(c[2]), "+f"(c[3])
        : "r"(a0), "r"(a1), "r"(a2), "r"(a3), "r"(b0), "r"(b1));
}

__global__ __launch_bounds__(256)
void qkv_gemm_fused(const float* __restrict__ h,
                    const float* __restrict__ Wq, const float* __restrict__ bq,
                    const float* __restrict__ Wk, const float* __restrict__ bk,
                    const float* __restrict__ Wv, const float* __restrict__ bv,
                    int n_nodes)
{
    extern __shared__ __half smemh[];
    __half* as = smemh;                  // as[r*PAD_H + k]
    __half* ws = smemh + 128 * PAD_H;    // ws[n*PAD_H + k]  (W transposed)

    const int row0 = blockIdx.x * 128;
    const int tid  = threadIdx.x;

    const float* Wmat[3]  = {Wq, Wk, Wv};
    const float* Bvec[3]  = {bq, bk, bv};

    // Stage A (h tile) once.
    #pragma unroll
    for (int i = 0; i < 64; i++) {
        int lin = tid + i * 256;
        int r = lin >> 7;
        int k = lin & 127;
        float v = 0.0f;
        int gr = row0 + r;
        if (gr < n_nodes) v = h[gr * IND + k];
        as[r * PAD_H + k] = __float2half_rn(v);
    }
    // Stage W for phase 0.
    {
        const float* W = Wmat[0];
        #pragma unroll
        for (int i = 0; i < 64; i++) {
            int lin = tid + i * 256;
            int k = lin >> 7;
            int n = lin & 127;
            ws[n * PAD_H + k] = __float2half_rn(W[k * HD + n]);
        }
    }
    __syncthreads();

    const int warp   = tid >> 5;
    const int lane   = tid & 31;
    const int g      = lane >> 2;       // 0..7
    const int t      = lane & 3;        // 0..3
    const int warp_m = warp & 3;        // 0..3
    const int warp_n = warp >> 2;       // 0..1

    const __half* a_base = as + (warp_m * 32 + g) * PAD_H + 2 * t;
    const __half* b_base = ws + (warp_n * 64 + g) * PAD_H + 2 * t;

    #pragma unroll
    for (int w = 0; w < 3; w++) {
        const float* bias = Bvec[w];

        float c[2][8][4];
        #pragma unroll
        for (int ni = 0; ni < 8; ni++) {
            int col = warp_n * 64 + ni * 8 + 2 * t;
            float b0 = bias[col];
            float b1 = bias[col + 1];
            #pragma unroll
            for (int mi = 0; mi < 2; mi++) {
                c[mi][ni][0] = b0; c[mi][ni][1] = b1;
                c[mi][ni][2] = b0; c[mi][ni][3] = b1;
            }
        }

        #pragma unroll
        for (int kk = 0; kk < 8; kk++) {
            const int k0 = kk * 16;

            uint32_t a[2][4];
            #pragma unroll
            for (int mi = 0; mi < 2; mi++) {
                const __half* ap = a_base + mi * 16 * PAD_H + k0;
                a[mi][0] = *(const uint32_t*)(ap);
                a[mi][1] = *(const uint32_t*)(ap + 8 * PAD_H);
                a[mi][2] = *(const uint32_t*)(ap + 8);
                a[mi][3] = *(const uint32_t*)(ap + 8 * PAD_H + 8);
            }

            uint32_t b[8][2];
            #pragma unroll
            for (int ni = 0; ni < 8; ni++) {
                const __half* bp = b_base + ni * 8 * PAD_H + k0;
                b[ni][0] = *(const uint32_t*)(bp);
                b[ni][1] = *(const uint32_t*)(bp + 8);
            }

            #pragma unroll
            for (int mi = 0; mi < 2; mi++)
                #pragma unroll
                for (int ni = 0; ni < 8; ni++)
                    mma_f16(c[mi][ni], a[mi][0], a[mi][1], a[mi][2], a[mi][3],
                            b[ni][0], b[ni][1]);
        }

        // Epilogue for this phase.
        if (w == 0) {
            #pragma unroll
            for (int mi = 0; mi < 2; mi++) {
                int r_lo = row0 + warp_m * 32 + mi * 16 + g;
                #pragma unroll
                for (int ni = 0; ni < 8; ni++) {
                    int col = warp_n * 64 + ni * 8 + 2 * t;
                    if (r_lo < n_nodes)
                        *(float2*)&g_Q[(size_t)r_lo * HD + col] =
                            make_float2(c[mi][ni][0], c[mi][ni][1]);
                    if (r_lo + 8 < n_nodes)
                        *(float2*)&g_Q[(size_t)(r_lo + 8) * HD + col] =
                            make_float2(c[mi][ni][2], c[mi][ni][3]);
                }
            }
        } else {
            const int kvofs = (w == 1) ? 0 : 4;  // K at 0..3, V at 4..7
            #pragma unroll
            for (int mi = 0; mi < 2; mi++) {
                int r_lo = row0 + warp_m * 32 + mi * 16 + g;
                #pragma unroll
                for (int ni = 0; ni < 8; ni++) {
                    int col = warp_n * 64 + ni * 8 + 2 * t;       // even
                    int ofs = (col >> 2) * 8 + (col & 3) + kvofs; // contiguous pair
                    if (r_lo < n_nodes)
                        *(__half2*)&g_KV[(size_t)r_lo * 256 + ofs] =
                            __floats2half2_rn(c[mi][ni][0], c[mi][ni][1]);
                    if (r_lo + 8 < n_nodes)
                        *(__half2*)&g_KV[(size_t)(r_lo + 8) * 256 + ofs] =
                            __floats2half2_rn(c[mi][ni][2], c[mi][ni][3]);
                }
            }
        }

        // Re-stage W for the next phase (all warps done reading ws).
        if (w < 2) {
            __syncthreads();
            const float* Wn = Wmat[w + 1];
            #pragma unroll
            for (int i = 0; i < 64; i++) {
                int lin = tid + i * 256;
                int k = lin >> 7;
                int n = lin & 127;
                ws[n * PAD_H + k] = __float2half_rn(Wn[k * HD + n]);
            }
            __syncthreads();
        }
    }
}

// ---------------------------------------------------------------------------
// hist: dst-degree histogram, 4 edges/thread via int4 (MLP=4 on the REDGs).
// ---------------------------------------------------------------------------
__global__ __launch_bounds__(256)
void hist_kernel(const int* __restrict__ dst, int n_edges)
{
    int q = blockIdx.x * blockDim.x + threadIdx.x;   // quad index
    int e0 = q * 4;
    if (e0 + 4 <= n_edges) {
        int4 d4 = __ldg((const int4*)(dst + e0));
        atomicAdd(&g_deg[d4.x], 1);
        atomicAdd(&g_deg[d4.y], 1);
        atomicAdd(&g_deg[d4.z], 1);
        atomicAdd(&g_deg[d4.w], 1);
    } else {
        for (int e = e0; e < n_edges; e++)
            atomicAdd(&g_deg[__ldg(dst + e)], 1);
    }
}

// ---------------------------------------------------------------------------
// scan1: per-block exclusive scan of g_deg (1024/block), emits block sums,
// and ZEROES g_deg behind itself (restores the all-zero invariant).
// ---------------------------------------------------------------------------
__global__ __launch_bounds__(1024)
void scan1_kernel(int n)
{
    __shared__ int wsum[32];
    int tid  = threadIdx.x;
    int lane = tid & 31, wid = tid >> 5;
    int i = blockIdx.x * 1024 + tid;
    int v = 0;
    if (i < n) {
        v = g_deg[i];
        g_deg[i] = 0;                 // self-restore for the next call
    }
    int x = v;
    #pragma unroll
    for (int o = 1; o < 32; o <<= 1) {
        int y = __shfl_up_sync(0xffffffffu, x, o);
        if (lane >= o) x += y;
    }
    if (lane == 31) wsum[wid] = x;
    __syncthreads();
    if (wid == 0) {
        int w = wsum[lane];
        #pragma unroll
        for (int o = 1; o < 32; o <<= 1) {
            int y = __shfl_up_sync(0xffffffffu, w, o);
            if (lane >= o) w += y;
        }
        wsum[lane] = w;  // inclusive warp totals
    }
    __syncthreads();
    int woff = (wid > 0) ? wsum[wid - 1] : 0;
    if (i < n) g_scantmp[i] = woff + x - v;          // exclusive within block
    if (tid == 1023) g_bsums[blockIdx.x] = woff + x; // block total
}

// ---------------------------------------------------------------------------
// scan23: every block redundantly exclusive-scans the (<=64) block sums
// in-register, applies the offset, emits rowstart + cursor.
// ---------------------------------------------------------------------------
__global__ __launch_bounds__(1024)
void scan23_kernel(int n, int nb, int n_edges)
{
    __shared__ int boffs_s[64];
    __shared__ int wtot;
    int tid = threadIdx.x;
    if (tid < 64) {
        int lane = tid & 31;
        int v = (tid < nb) ? g_bsums[tid] : 0;
        int x = v;
        #pragma unroll
        for (int o = 1; o < 32; o <<= 1) {
            int y = __shfl_up_sync(0xffffffffu, x, o);
            if (lane >= o) x += y;
        }
        if (tid == 31) wtot = x;      // total of first warp's 32 sums
        __syncwarp();
        boffs_s[tid] = x - v;         // exclusive within each 32-group
    }
    __syncthreads();
    int i = blockIdx.x * 1024 + tid;
    int blk = i >> 10;
    int boff = boffs_s[blk] + ((blk >= 32) ? wtot : 0);
    if (i < n) {
        int r = g_scantmp[i] + boff;
        g_rowstart[i] = r;
        g_cursor[i]   = r;
    }
    if (i == n) g_rowstart[n] = n_edges;
}

// ---------------------------------------------------------------------------
// scatter: 4 edges/thread via int4 loads -> 4 independent ATOMGs in flight.
// ---------------------------------------------------------------------------
__global__ __launch_bounds__(256)
void scatter_kernel(const int* __restrict__ src, const int* __restrict__ dst,
                    int n_edges)
{
    int q = blockIdx.x * blockDim.x + threadIdx.x;
    int e0 = q * 4;
    if (e0 + 4 <= n_edges) {
        int4 s4 = __ldg((const int4*)(src + e0));
        int4 d4 = __ldg((const int4*)(dst + e0));
        int p0 = atomicAdd(&g_cursor[d4.x], 1);
        int p1 = atomicAdd(&g_cursor[d4.y], 1);
        int p2 = atomicAdd(&g_cursor[d4.z], 1);
        int p3 = atomicAdd(&g_cursor[d4.w], 1);
        g_src_sorted[p0] = s4.x;
        g_src_sorted[p1] = s4.y;
        g_src_sorted[p2] = s4.z;
        g_src_sorted[p3] = s4.w;
    } else {
        for (int e = e0; e < n_edges; e++) {
            int pos = atomicAdd(&g_cursor[__ldg(dst + e)], 1);
            g_src_sorted[pos] = __ldg(src + e);
        }
    }
}

// ---------------------------------------------------------------------------
// Aggregation: one warp per destination node, no atomics.
// ONE uint4 (16B) gather per (edge, lane) fetches both the K and V chunk
// (interleaved layout). Chunks of 8 edges -> 8 independent LDG.128 in flight.
// Node stride in uint4 units: 32 (256 halves).
// ---------------------------------------------------------------------------
__device__ __forceinline__ float4 h4lo(uint4 u) {   // K halves 0..3
    float2 a = __half22float2(*(__half2*)&u.x);
    float2 b = __half22float2(*(__half2*)&u.y);
    return make_float4(a.x, a.y, b.x, b.y);
}
__device__ __forceinline__ float4 h4hi(uint4 u) {   // V halves 4..7
    float2 a = __half22float2(*(__half2*)&u.z);
    float2 b = __half22float2(*(__half2*)&u.w);
    return make_float4(a.x, a.y, b.x, b.y);
}

__global__ __launch_bounds__(256)
void aggregate_kernel(float* __restrict__ out, int n_nodes)
{
    int gtid = blockIdx.x * blockDim.x + threadIdx.x;
    int d    = gtid >> 5;
    int lane = gtid & 31;
    if (d >= n_nodes) return;

    const float4* Q4  = (const float4*)g_Q;
    const uint4*  KV4 = (const uint4*)g_KV;  // node stride: 32 uint4 (256 half)

    float4 q = __ldg(&Q4[(size_t)d * 32 + lane]);
    int beg = g_rowstart[d];
    int end = g_rowstart[d + 1];

    float4 acc = make_float4(0.f, 0.f, 0.f, 0.f);

    int e = beg;
    for (; e + 8 <= end; e += 8) {
        int s[8];
        #pragma unroll
        for (int j = 0; j < 8; j++) s[j] = __ldg(g_src_sorted + e + j);

        uint4 kv[8];
        #pragma unroll
        for (int j = 0; j < 8; j++)
            kv[j] = __ldg(&KV4[(size_t)s[j] * 32 + lane]);

        float p[8];
        #pragma unroll
        for (int j = 0; j < 8; j++) {
            float4 k = h4lo(kv[j]);
            p[j] = k.x*q.x + k.y*q.y + k.z*q.z + k.w*q.w;
        }
        #pragma unroll
        for (int j = 0; j < 8; j++) p[j] += __shfl_xor_sync(0xffffffffu, p[j], 1);
        #pragma unroll
        for (int j = 0; j < 8; j++) p[j] += __shfl_xor_sync(0xffffffffu, p[j], 2);
        #pragma unroll
        for (int j = 0; j < 8; j++) {
            float pj = p[j] * 0.25f;             // 1/sqrt(16)
            float4 v = h4hi(kv[j]);
            acc.x += pj * v.x; acc.y += pj * v.y;
            acc.z += pj * v.z; acc.w += pj * v.w;
        }
    }
    for (; e + 4 <= end; e += 4) {
        int s0 = __ldg(g_src_sorted + e);
        int s1 = __ldg(g_src_sorted + e + 1);
        int s2 = __ldg(g_src_sorted + e + 2);
        int s3 = __ldg(g_src_sorted + e + 3);

        uint4 kv0 = __ldg(&KV4[(size_t)s0 * 32 + lane]);
        uint4 kv1 = __ldg(&KV4[(size_t)s1 * 32 + lane]);
        uint4 kv2 = __ldg(&KV4[(size_t)s2 * 32 + lane]);
        uint4 kv3 = __ldg(&KV4[(size_t)s3 * 32 + lane]);

        float4 k0 = h4lo(kv0), k1 = h4lo(kv1), k2 = h4lo(kv2), k3 = h4lo(kv3);

        float p0 = k0.x*q.x + k0.y*q.y + k0.z*q.z + k0.w*q.w;
        float p1 = k1.x*q.x + k1.y*q.y + k1.z*q.z + k1.w*q.w;
        float p2 = k2.x*q.x + k2.y*q.y + k2.z*q.z + k2.w*q.w;
        float p3 = k3.x*q.x + k3.y*q.y + k3.z*q.z + k3.w*q.w;

        p0 += __shfl_xor_sync(0xffffffffu, p0, 1);
        p1 += __shfl_xor_sync(0xffffffffu, p1, 1);
        p2 += __shfl_xor_sync(0xffffffffu, p2, 1);
        p3 += __shfl_xor_sync(0xffffffffu, p3, 1);
        p0 += __shfl_xor_sync(0xffffffffu, p0, 2);
        p1 += __shfl_xor_sync(0xffffffffu, p1, 2);
        p2 += __shfl_xor_sync(0xffffffffu, p2, 2);
        p3 += __shfl_xor_sync(0xffffffffu, p3, 2);
        p0 *= 0.25f; p1 *= 0.25f; p2 *= 0.25f; p3 *= 0.25f;

        float4 v0 = h4hi(kv0), v1 = h4hi(kv1), v2 = h4hi(kv2), v3 = h4hi(kv3);

        acc.x += p0*v0.x + p1*v1.x + p2*v2.x + p3*v3.x;
        acc.y += p0*v0.y + p1*v1.y + p2*v2.y + p3*v3.y;
        acc.z += p0*v0.z + p1*v1.z + p2*v2.z + p3*v3.z;
        acc.w += p0*v0.w + p1*v1.w + p2*v2.w + p3*v3.w;
    }
    for (; e < end; e++) {
        int s = __ldg(g_src_sorted + e);
        uint4 kv = __ldg(&KV4[(size_t)s * 32 + lane]);
        float4 k = h4lo(kv);
        float p = k.x*q.x + k.y*q.y + k.z*q.z + k.w*q.w;
        p += __shfl_xor_sync(0xffffffffu, p, 1);
        p += __shfl_xor_sync(0xffffffffu, p, 2);
        p *= 0.25f;
        float4 v = h4hi(kv);
        acc.x += p*v.x; acc.y += p*v.y; acc.z += p*v.z; acc.w += p*v.w;
    }

    *(float4*)&out[(size_t)d * HD + lane * 4] = acc;
}

// ---------------------------------------------------------------------------
// Launch. Two parallel branches inside the captured graph:
//   branch A (side stream): qkv_gemm_fused
//   branch B (main stream): hist -> scan1 -> scan23 -> scatter
// joined before aggregate.
// ---------------------------------------------------------------------------
extern "C" void kernel_launch(void* const* d_in, const int* in_sizes, int n_in,
                              void* d_out, int out_size)
{
    const float* h   = (const float*)d_in[0];
    const int*   src = (const int*)  d_in[1];
    const int*   dst = (const int*)  d_in[2];
    const float* Wq  = (const float*)d_in[3];
    const float* bq  = (const float*)d_in[4];
    const float* Wk  = (const float*)d_in[5];
    const float* bk  = (const float*)d_in[6];
    const float* Wv  = (const float*)d_in[7];
    const float* bv  = (const float*)d_in[8];
    float* out = (float*)d_out;

    int n_nodes = in_sizes[0] / IND;   // 50000
    int n_edges = in_sizes[1];         // 800000

    cudaFuncSetAttribute(qkv_gemm_fused,
                         cudaFuncAttributeMaxDynamicSharedMemorySize,
                         GEMM_SMEM_BYTES);

    static cudaStream_t side = nullptr;
    static cudaEvent_t  evFork = nullptr, evGemm = nullptr;
    if (side == nullptr) {
        cudaStreamCreateWithFlags(&side, cudaStreamNonBlocking);
        cudaEventCreateWithFlags(&evFork, cudaEventDisableTiming);
        cudaEventCreateWithFlags(&evGemm, cudaEventDisableTiming);
    }

    // Fork: fused GEMM branch on side stream.
    cudaEventRecord(evFork, 0);
    cudaStreamWaitEvent(side, evFork, 0);
    int gb = (n_nodes + 127) / 128;
    qkv_gemm_fused<<<gb, 256, GEMM_SMEM_BYTES, side>>>(h, Wq, bq, Wk, bk,
                                                       Wv, bv, n_nodes);
    cudaEventRecord(evGemm, side);

    // CSR branch on main stream (concurrent with GEMM).
    int nquad = (n_edges + 3) / 4;
    int qb = (nquad + 255) / 256;
    hist_kernel<<<qb, 256>>>(dst, n_edges);

    int nb = (n_nodes + 1023) / 1024;              // 49 for N=50000
    scan1_kernel<<<nb, 1024>>>(n_nodes);
    int nb1 = (n_nodes + 1 + 1023) / 1024;
    scan23_kernel<<<nb1, 1024>>>(n_nodes, nb, n_edges);

    scatter_kernel<<<qb, 256>>>(src, dst, n_edges);

    // Join: aggregate needs both branches.
    cudaStreamWaitEvent(0, evGemm, 0);
    int ablocks = (n_nodes * 32 + 255) / 256;
    aggregate_kernel<<<ablocks, 256>>>(out, n_nodes);
}